// round 4
// baseline (speedup 1.0000x reference)
#include <cuda_runtime.h>
#include <cuda_bf16.h>
#include <math.h>
#include <stdint.h>

// ---------------------------------------------------------------------------
// Problem constants
// ---------------------------------------------------------------------------
#define B        8192
#define NF       1725          // 8*106 + 10*60 + 8*33 + 13
#define LDH      1728          // padded leading dim (div by 16)
#define N1       1024
#define N2       512
#define N3       256
#define NCROSS   4
#define EPS      1e-5f
#define NCHUNK   32            // row chunks for column stats
#define ROWS_PER_CHUNK (B / NCHUNK)

// ---------------------------------------------------------------------------
// Scratch (device globals; no allocation allowed)
// ---------------------------------------------------------------------------
__device__ float g_h   [B * LDH];        // gathered + BN'd features
__device__ float g_w1p [LDH * N1];       // padded W1 (rows 1725..1727 = 0)
__device__ float g_z1  [B * N1];
__device__ float g_z2  [B * N2];
__device__ float g_z3  [B * N3];
__device__ float g_cross_partial[B];     // out_cross . Wout[:1725]
__device__ float g_psum[NCHUNK * LDH];
__device__ float g_psq [NCHUNK * LDH];
__device__ float g_mean[LDH];
__device__ float g_rstd[LDH];

// ---------------------------------------------------------------------------
// 1. Gather embeddings + dense into h (row-major B x LDH, pad cols zeroed)
// ---------------------------------------------------------------------------
__global__ void gather_kernel(const int* __restrict__ sparse,
                              const float* __restrict__ dense,
                              const float* __restrict__ emb_a,
                              const float* __restrict__ emb_b,
                              const float* __restrict__ emb_c)
{
    __shared__ int sp[26];
    const int row = blockIdx.x;
    if (threadIdx.x < 26) sp[threadIdx.x] = sparse[row * 26 + threadIdx.x];
    __syncthreads();

    float* hr = g_h + (size_t)row * LDH;
    for (int j = threadIdx.x; j < LDH; j += blockDim.x) {
        float v;
        if (j < 848) {                       // emb_a: 8 fields x 106
            int f = j / 106, c = j - f * 106;
            int idx = sp[f];
            v = emb_a[((size_t)f * 100000 + idx) * 106 + c];
        } else if (j < 1448) {               // emb_b: 10 fields x 60
            int t = j - 848;
            int f = t / 60, c = t - f * 60;
            int idx = sp[8 + f];
            v = emb_b[((size_t)f * 10000 + idx) * 60 + c];
        } else if (j < 1712) {               // emb_c: 8 fields x 33
            int t = j - 1448;
            int f = t / 33, c = t - f * 33;
            int idx = sp[18 + f];
            v = emb_c[((size_t)f * 1000 + idx) * 33 + c];
        } else if (j < 1725) {               // dense
            v = dense[row * 13 + (j - 1712)];
        } else {
            v = 0.0f;                        // pad
        }
        hr[j] = v;
    }
}

// ---------------------------------------------------------------------------
// 2. Column stats (deterministic two-pass), then normalize (+optional relu)
// ---------------------------------------------------------------------------
__global__ void colstats_partial(const float* __restrict__ X, int ld, int ncols)
{
    int col = blockIdx.x * blockDim.x + threadIdx.x;
    if (col >= ncols) return;
    int r0 = blockIdx.y * ROWS_PER_CHUNK;
    float s = 0.f, q = 0.f;
    const float* p = X + (size_t)r0 * ld + col;
    for (int r = 0; r < ROWS_PER_CHUNK; r++) {
        float v = p[(size_t)r * ld];
        s += v; q += v * v;
    }
    g_psum[blockIdx.y * ncols + col] = s;
    g_psq [blockIdx.y * ncols + col] = q;
}

__global__ void colstats_final(int ncols)
{
    int col = blockIdx.x * blockDim.x + threadIdx.x;
    if (col >= ncols) return;
    float s = 0.f, q = 0.f;
    for (int c = 0; c < NCHUNK; c++) {
        s += g_psum[c * ncols + col];
        q += g_psq [c * ncols + col];
    }
    float mean = s * (1.0f / B);
    float var  = q * (1.0f / B) - mean * mean;
    g_mean[col] = mean;
    g_rstd[col] = rsqrtf(var + EPS);
}

__global__ void bn_apply_v4(float4* __restrict__ X, int ld4, long total4, int relu)
{
    long i = (long)blockIdx.x * blockDim.x + threadIdx.x;
    if (i >= total4) return;
    int c = (int)(i % ld4) * 4;
    float4 v = X[i];
    v.x = (v.x - g_mean[c + 0]) * g_rstd[c + 0];
    v.y = (v.y - g_mean[c + 1]) * g_rstd[c + 1];
    v.z = (v.z - g_mean[c + 2]) * g_rstd[c + 2];
    v.w = (v.w - g_mean[c + 3]) * g_rstd[c + 3];
    if (relu) {
        v.x = fmaxf(v.x, 0.f); v.y = fmaxf(v.y, 0.f);
        v.z = fmaxf(v.z, 0.f); v.w = fmaxf(v.w, 0.f);
    }
    X[i] = v;
}

// ---------------------------------------------------------------------------
// 3. Fused cross network (4 layers) + cross contribution to final logit.
// ---------------------------------------------------------------------------
__global__ __launch_bounds__(256)
void cross_kernel(const float* __restrict__ cw,
                  const float* __restrict__ cb,
                  const float* __restrict__ wout)
{
    __shared__ float x0[NF];
    __shared__ float xi[NF];
    __shared__ float red[256];
    const int row = blockIdx.x;
    const int tid = threadIdx.x;

    const float* hr = g_h + (size_t)row * LDH;
    for (int j = tid; j < NF; j += 256) {
        float v = hr[j];
        x0[j] = v; xi[j] = v;
    }
    __syncthreads();

    for (int L = 0; L < NCROSS; L++) {
        const float* w = cw + L * NF;
        float s = 0.f;
        for (int j = tid; j < NF; j += 256) s += xi[j] * w[j];
        red[tid] = s;
        __syncthreads();
        #pragma unroll
        for (int off = 128; off > 0; off >>= 1) {
            if (tid < off) red[tid] += red[tid + off];
            __syncthreads();
        }
        float dot = red[0];
        const float* b = cb + L * NF;
        for (int j = tid; j < NF; j += 256)
            xi[j] = fmaf(x0[j], dot, b[j] + xi[j]);
        __syncthreads();
    }

    float s = 0.f;
    for (int j = tid; j < NF; j += 256) s += xi[j] * wout[j];
    red[tid] = s;
    __syncthreads();
    #pragma unroll
    for (int off = 128; off > 0; off >>= 1) {
        if (tid < off) red[tid] += red[tid + off];
        __syncthreads();
    }
    if (tid == 0) g_cross_partial[row] = red[0];
}

// ---------------------------------------------------------------------------
// 4. Tensor-core GEMM: C = A(fp32->tf32) @ (Bhi + Blo) + bias
//    mma.sync.m16n8k8 tf32. BM=128, BN=128, BK=16, 256 threads (8 warps).
//    Warp tile 64x32 (4x4 m16n8 frags). B split hi/lo for fp32-class accuracy.
//    Requires M%128==0, N%128==0, K%16==0.
// ---------------------------------------------------------------------------
__device__ __forceinline__ uint32_t f2tf32(float v) {
    uint32_t r;
    asm("cvt.rna.tf32.f32 %0, %1;" : "=r"(r) : "f"(v));
    return r;
}

#define MMA_TF32(d0,d1,d2,d3,a0,a1,a2,a3,b0,b1)                         \
    asm volatile("mma.sync.aligned.m16n8k8.row.col.f32.tf32.tf32.f32 "   \
        "{%0,%1,%2,%3}, {%4,%5,%6,%7}, {%8,%9}, {%0,%1,%2,%3};\n"        \
        : "+f"(d0), "+f"(d1), "+f"(d2), "+f"(d3)                         \
        : "r"(a0), "r"(a1), "r"(a2), "r"(a3), "r"(b0), "r"(b1))

#define SMS 136   // smem row stride (128 + 8 pad) -> conflict-free frag loads

__global__ __launch_bounds__(256, 1)
void tgemm_bias(int M, int N, int K,
                const float* __restrict__ A, int lda,
                const float* __restrict__ Bm, int ldb,
                const float* __restrict__ bias,
                float* __restrict__ C, int ldc)
{
    __shared__ float As[16 * SMS];
    __shared__ float Bh[16 * SMS];
    __shared__ float Bl[16 * SMS];

    const int tid  = threadIdx.x;
    const int lane = tid & 31;
    const int warp = tid >> 5;
    const int wm = warp >> 2;          // 0..1
    const int wn = warp & 3;           // 0..3
    const int g  = lane >> 2;          // 0..7
    const int tg = lane & 3;           // 0..3

    // global load mapping
    const int arow = tid >> 1;                 // 0..127
    const int acol = (tid & 1) * 8;            // 0 or 8
    const int brow = tid >> 4;                 // 0..15
    const int bcol = (tid & 15) * 8;           // 0..120

    const float* Abase = A + ((size_t)blockIdx.y * 128 + arow) * lda + acol;
    const float* Bbase = Bm + (size_t)blockIdx.x * 128 + bcol;

    float acc[4][4][4];
    #pragma unroll
    for (int i = 0; i < 4; i++)
        #pragma unroll
        for (int j = 0; j < 4; j++)
            #pragma unroll
            for (int c = 0; c < 4; c++) acc[i][j][c] = 0.f;

    float4 ap0 = *(const float4*)(Abase);
    float4 ap1 = *(const float4*)(Abase + 4);
    float4 bp0 = *(const float4*)(Bbase + (size_t)brow * ldb);
    float4 bp1 = *(const float4*)(Bbase + (size_t)brow * ldb + 4);

    for (int k0 = 0; k0 < K; k0 += 16) {
        __syncthreads();   // previous compute done before overwriting smem

        // ---- store A tile (transposed to [k][m]) as rna-tf32 ----
        {
            float av[8] = {ap0.x, ap0.y, ap0.z, ap0.w, ap1.x, ap1.y, ap1.z, ap1.w};
            #pragma unroll
            for (int j = 0; j < 8; j++)
                As[(acol + j) * SMS + arow] = __uint_as_float(f2tf32(av[j]));
        }
        // ---- store B tile hi/lo ----
        {
            float bv[8] = {bp0.x, bp0.y, bp0.z, bp0.w, bp1.x, bp1.y, bp1.z, bp1.w};
            #pragma unroll
            for (int j = 0; j < 8; j++) {
                uint32_t hi = f2tf32(bv[j]);
                float hif = __uint_as_float(hi);
                uint32_t lo = f2tf32(bv[j] - hif);
                Bh[brow * SMS + bcol + j] = hif;
                Bl[brow * SMS + bcol + j] = __uint_as_float(lo);
            }
        }

        // ---- prefetch next tile ----
        if (k0 + 16 < K) {
            const float* an = Abase + (k0 + 16);
            ap0 = *(const float4*)(an);
            ap1 = *(const float4*)(an + 4);
            const float* bn = Bbase + (size_t)(k0 + 16 + brow) * ldb;
            bp0 = *(const float4*)(bn);
            bp1 = *(const float4*)(bn + 4);
        }
        __syncthreads();

        // ---- compute: 2 k-steps of 8 ----
        #pragma unroll
        for (int ks = 0; ks < 2; ks++) {
            const int kb = ks * 8;
            uint32_t af[4][4];
            #pragma unroll
            for (int mt = 0; mt < 4; mt++) {
                int m = wm * 64 + mt * 16 + g;
                af[mt][0] = __float_as_uint(As[(kb + tg    ) * SMS + m    ]);
                af[mt][1] = __float_as_uint(As[(kb + tg    ) * SMS + m + 8]);
                af[mt][2] = __float_as_uint(As[(kb + tg + 4) * SMS + m    ]);
                af[mt][3] = __float_as_uint(As[(kb + tg + 4) * SMS + m + 8]);
            }
            uint32_t bfh[4][2], bfl[4][2];
            #pragma unroll
            for (int nt = 0; nt < 4; nt++) {
                int n = wn * 32 + nt * 8 + g;
                bfh[nt][0] = __float_as_uint(Bh[(kb + tg    ) * SMS + n]);
                bfh[nt][1] = __float_as_uint(Bh[(kb + tg + 4) * SMS + n]);
                bfl[nt][0] = __float_as_uint(Bl[(kb + tg    ) * SMS + n]);
                bfl[nt][1] = __float_as_uint(Bl[(kb + tg + 4) * SMS + n]);
            }
            #pragma unroll
            for (int mt = 0; mt < 4; mt++)
                #pragma unroll
                for (int nt = 0; nt < 4; nt++) {
                    MMA_TF32(acc[mt][nt][0], acc[mt][nt][1], acc[mt][nt][2], acc[mt][nt][3],
                             af[mt][0], af[mt][1], af[mt][2], af[mt][3],
                             bfh[nt][0], bfh[nt][1]);
                    MMA_TF32(acc[mt][nt][0], acc[mt][nt][1], acc[mt][nt][2], acc[mt][nt][3],
                             af[mt][0], af[mt][1], af[mt][2], af[mt][3],
                             bfl[nt][0], bfl[nt][1]);
                }
        }
    }

    // ---- epilogue: + bias, store ----
    #pragma unroll
    for (int mt = 0; mt < 4; mt++) {
        int row0 = blockIdx.y * 128 + wm * 64 + mt * 16 + g;
        #pragma unroll
        for (int nt = 0; nt < 4; nt++) {
            int col = blockIdx.x * 128 + wn * 32 + nt * 8 + tg * 2;
            float b0 = bias[col], b1 = bias[col + 1];
            float2 v0 = make_float2(acc[mt][nt][0] + b0, acc[mt][nt][1] + b1);
            float2 v1 = make_float2(acc[mt][nt][2] + b0, acc[mt][nt][3] + b1);
            *(float2*)(C + (size_t)row0 * ldc + col)       = v0;
            *(float2*)(C + (size_t)(row0 + 8) * ldc + col) = v1;
        }
    }
}

// ---------------------------------------------------------------------------
// 5. Pad W1 (1725 x 1024) into g_w1p (1728 x 1024), zero tail rows
// ---------------------------------------------------------------------------
__global__ void pad_w1(const float* __restrict__ W1)
{
    long i = (long)blockIdx.x * blockDim.x + threadIdx.x;
    long total = (long)LDH * N1;
    if (i >= total) return;
    int k = (int)(i / N1);
    g_w1p[i] = (k < NF) ? W1[i] : 0.0f;
}

// ---------------------------------------------------------------------------
// 6. Final: logits = cross_partial + a3 . Wout[1725:1981]; sigmoid
// ---------------------------------------------------------------------------
__global__ void final_kernel(const float* __restrict__ wout_tail,
                             float* __restrict__ out)
{
    int row  = blockIdx.x * 8 + (threadIdx.x >> 5);
    int lane = threadIdx.x & 31;
    const float* r = g_z3 + (size_t)row * N3;
    float s = 0.f;
    #pragma unroll
    for (int j = lane; j < N3; j += 32) s += r[j] * wout_tail[j];
    #pragma unroll
    for (int off = 16; off > 0; off >>= 1)
        s += __shfl_down_sync(0xffffffffu, s, off);
    if (lane == 0) {
        float z = s + g_cross_partial[row];
        out[row] = 1.0f / (1.0f + expf(-z));
    }
}

// ---------------------------------------------------------------------------
// Launcher
// ---------------------------------------------------------------------------
extern "C" void kernel_launch(void* const* d_in, const int* in_sizes, int n_in,
                              void* d_out, int out_size)
{
    const int*   sparse  = (const int*)  d_in[0];
    const float* dense   = (const float*)d_in[1];
    const float* emb_a   = (const float*)d_in[2];
    const float* emb_b   = (const float*)d_in[3];
    const float* emb_c   = (const float*)d_in[4];
    const float* cross_w = (const float*)d_in[5];
    const float* cross_b = (const float*)d_in[6];
    const float* W1      = (const float*)d_in[7];
    const float* b1      = (const float*)d_in[8];
    const float* W2      = (const float*)d_in[9];
    const float* b2      = (const float*)d_in[10];
    const float* W3      = (const float*)d_in[11];
    const float* b3      = (const float*)d_in[12];
    const float* Wout    = (const float*)d_in[13];
    float* out = (float*)d_out;

    float *ph, *pw1p, *pz1, *pz2, *pz3;
    cudaGetSymbolAddress((void**)&ph,   g_h);
    cudaGetSymbolAddress((void**)&pw1p, g_w1p);
    cudaGetSymbolAddress((void**)&pz1,  g_z1);
    cudaGetSymbolAddress((void**)&pz2,  g_z2);
    cudaGetSymbolAddress((void**)&pz3,  g_z3);

    // ---- pad W1 ----
    {
        long total = (long)LDH * N1;
        pad_w1<<<(int)((total + 255) / 256), 256>>>(W1);
    }

    // ---- gather ----
    gather_kernel<<<B, 256>>>(sparse, dense, emb_a, emb_b, emb_c);

    // ---- BN(h) ----
    {
        dim3 g((LDH + 127) / 128, NCHUNK);
        colstats_partial<<<g, 128>>>(ph, LDH, LDH);
        colstats_final<<<(LDH + 127) / 128, 128>>>(LDH);
        long t4 = (long)B * (LDH / 4);
        bn_apply_v4<<<(int)((t4 + 255) / 256), 256>>>((float4*)ph, LDH / 4, t4, 0);
    }

    // ---- cross network (fused with Wout head) ----
    cross_kernel<<<B, 256>>>(cross_w, cross_b, Wout);

    // ---- layer 1: z1 = h @ W1p + b1; BN; relu ----
    {
        dim3 grid(N1 / 128, B / 128);
        tgemm_bias<<<grid, 256>>>(B, N1, LDH, ph, LDH, pw1p, N1, b1, pz1, N1);
        dim3 g((N1 + 127) / 128, NCHUNK);
        colstats_partial<<<g, 128>>>(pz1, N1, N1);
        colstats_final<<<(N1 + 127) / 128, 128>>>(N1);
        long t4 = (long)B * (N1 / 4);
        bn_apply_v4<<<(int)((t4 + 255) / 256), 256>>>((float4*)pz1, N1 / 4, t4, 1);
    }

    // ---- layer 2 ----
    {
        dim3 grid(N2 / 128, B / 128);
        tgemm_bias<<<grid, 256>>>(B, N2, N1, pz1, N1, W2, N2, b2, pz2, N2);
        dim3 g((N2 + 127) / 128, NCHUNK);
        colstats_partial<<<g, 128>>>(pz2, N2, N2);
        colstats_final<<<(N2 + 127) / 128, 128>>>(N2);
        long t4 = (long)B * (N2 / 4);
        bn_apply_v4<<<(int)((t4 + 255) / 256), 256>>>((float4*)pz2, N2 / 4, t4, 1);
    }

    // ---- layer 3 ----
    {
        dim3 grid(N3 / 128, B / 128);
        tgemm_bias<<<grid, 256>>>(B, N3, N2, pz2, N2, W3, N3, b3, pz3, N3);
        dim3 g((N3 + 127) / 128, NCHUNK);
        colstats_partial<<<g, 128>>>(pz3, N3, N3);
        colstats_final<<<(N3 + 127) / 128, 128>>>(N3);
        long t4 = (long)B * (N3 / 4);
        bn_apply_v4<<<(int)((t4 + 255) / 256), 256>>>((float4*)pz3, N3 / 4, t4, 1);
    }

    // ---- final head ----
    final_kernel<<<B / 8, 256>>>(Wout + NF, out);
}

// round 10
// speedup vs baseline: 1.8798x; 1.8798x over previous
#include <cuda_runtime.h>
#include <cuda_bf16.h>
#include <math.h>
#include <stdint.h>

// ---------------------------------------------------------------------------
// Problem constants
// ---------------------------------------------------------------------------
#define B        8192
#define NF       1725          // 8*106 + 10*60 + 8*33 + 13
#define LDH      1728          // padded leading dim (div by 64)
#define N1       1024
#define N2       512
#define N3       256
#define NCROSS   4
#define EPS      1e-5f
#define NCHUNK   32
#define ROWS_PER_CHUNK (B / NCHUNK)

// ---------------------------------------------------------------------------
// Scratch (device globals; no allocation allowed)
// ---------------------------------------------------------------------------
__device__ float g_h   [B * LDH];            // fp32 normalized features (cross)
__device__ float g_z1  [B * N1];
__device__ float g_z2  [B * N2];
__device__ float g_z3  [B * N3];
__device__ float g_cross_partial[B];
__device__ float g_psum[NCHUNK * LDH];
__device__ float g_psq [NCHUNK * LDH];
__device__ float g_mean[LDH];
__device__ float g_rstd[LDH];

// bf16 hi/lo activations (uint4 = 8 bf16)
__device__ uint4 g_ah [B * LDH / 8];
__device__ uint4 g_al [B * LDH / 8];
__device__ uint4 g_z1h[B * N1 / 8];
__device__ uint4 g_z1l[B * N1 / 8];
__device__ uint4 g_z2h[B * N2 / 8];
__device__ uint4 g_z2l[B * N2 / 8];
// bf16 hi/lo transposed weights (row n, K contiguous)
__device__ uint4 g_w1h[N1 * LDH / 8];
__device__ uint4 g_w1l[N1 * LDH / 8];
__device__ uint4 g_w2h[N2 * N1 / 8];
__device__ uint4 g_w2l[N2 * N1 / 8];
__device__ uint4 g_w3h[N3 * N2 / 8];
__device__ uint4 g_w3l[N3 * N2 / 8];

// ---------------------------------------------------------------------------
// PTX helpers (legacy tensor path: compute_103-safe)
// ---------------------------------------------------------------------------
__device__ __forceinline__ uint32_t smem_u32(const void* p) {
    uint32_t a;
    asm("{ .reg .u64 t; cvta.to.shared.u64 t, %1; cvt.u32.u64 %0, t; }"
        : "=r"(a) : "l"(p));
    return a;
}

#define CP_ASYNC16(saddr, gptr) \
    asm volatile("cp.async.cg.shared.global [%0], [%1], 16;" :: "r"(saddr), "l"(gptr))
#define CP_COMMIT()  asm volatile("cp.async.commit_group;" ::: "memory")
#define CP_WAIT0()   asm volatile("cp.async.wait_group 0;" ::: "memory")

#define LDSM4(r0, r1, r2, r3, addr) \
    asm volatile("ldmatrix.sync.aligned.m8n8.x4.shared.b16 {%0,%1,%2,%3}, [%4];" \
        : "=r"(r0), "=r"(r1), "=r"(r2), "=r"(r3) : "r"(addr))

#define MMA_BF16(d, a, b) \
    asm volatile("mma.sync.aligned.m16n8k16.row.col.f32.bf16.bf16.f32 " \
        "{%0,%1,%2,%3},{%4,%5,%6,%7},{%8,%9},{%0,%1,%2,%3};" \
        : "+f"((d)[0]), "+f"((d)[1]), "+f"((d)[2]), "+f"((d)[3]) \
        : "r"((a)[0]), "r"((a)[1]), "r"((a)[2]), "r"((a)[3]),     \
          "r"((b)[0]), "r"((b)[1]))

// ---------------------------------------------------------------------------
// 1. Gather
// ---------------------------------------------------------------------------
__global__ void gather_kernel(const int* __restrict__ sparse,
                              const float* __restrict__ dense,
                              const float* __restrict__ emb_a,
                              const float* __restrict__ emb_b,
                              const float* __restrict__ emb_c)
{
    __shared__ int sp[26];
    const int row = blockIdx.x;
    if (threadIdx.x < 26) sp[threadIdx.x] = sparse[row * 26 + threadIdx.x];
    __syncthreads();

    float* hr = g_h + (size_t)row * LDH;
    for (int j = threadIdx.x; j < LDH; j += blockDim.x) {
        float v;
        if (j < 848) {
            int f = j / 106, c = j - f * 106;
            v = emb_a[((size_t)f * 100000 + sp[f]) * 106 + c];
        } else if (j < 1448) {
            int t = j - 848;
            int f = t / 60, c = t - f * 60;
            v = emb_b[((size_t)f * 10000 + sp[8 + f]) * 60 + c];
        } else if (j < 1712) {
            int t = j - 1448;
            int f = t / 33, c = t - f * 33;
            v = emb_c[((size_t)f * 1000 + sp[18 + f]) * 33 + c];
        } else if (j < 1725) {
            v = dense[row * 13 + (j - 1712)];
        } else {
            v = 0.0f;
        }
        hr[j] = v;
    }
}

// ---------------------------------------------------------------------------
// 2. Column stats + normalize
// ---------------------------------------------------------------------------
__global__ void colstats_partial(const float* __restrict__ X, int ld, int ncols)
{
    int col = blockIdx.x * blockDim.x + threadIdx.x;
    if (col >= ncols) return;
    int r0 = blockIdx.y * ROWS_PER_CHUNK;
    float s = 0.f, q = 0.f;
    const float* p = X + (size_t)r0 * ld + col;
    for (int r = 0; r < ROWS_PER_CHUNK; r++) {
        float v = p[(size_t)r * ld];
        s += v; q += v * v;
    }
    g_psum[blockIdx.y * ncols + col] = s;
    g_psq [blockIdx.y * ncols + col] = q;
}

__global__ void colstats_final(int ncols)
{
    int col = blockIdx.x * blockDim.x + threadIdx.x;
    if (col >= ncols) return;
    float s = 0.f, q = 0.f;
    for (int c = 0; c < NCHUNK; c++) {
        s += g_psum[c * ncols + col];
        q += g_psq [c * ncols + col];
    }
    float mean = s * (1.0f / B);
    float var  = q * (1.0f / B) - mean * mean;
    g_mean[col] = mean;
    g_rstd[col] = rsqrtf(var + EPS);
}

// normalize (+relu), optionally keep fp32, emit bf16 hi/lo pairs
__global__ void bn_apply_bf16(const float4* __restrict__ X, float4* __restrict__ Xout,
                              uint2* __restrict__ oh, uint2* __restrict__ ol,
                              int ld4, long total4, int relu)
{
    long i = (long)blockIdx.x * blockDim.x + threadIdx.x;
    if (i >= total4) return;
    int c = (int)(i % ld4) * 4;
    float4 v = X[i];
    v.x = (v.x - g_mean[c + 0]) * g_rstd[c + 0];
    v.y = (v.y - g_mean[c + 1]) * g_rstd[c + 1];
    v.z = (v.z - g_mean[c + 2]) * g_rstd[c + 2];
    v.w = (v.w - g_mean[c + 3]) * g_rstd[c + 3];
    if (relu) {
        v.x = fmaxf(v.x, 0.f); v.y = fmaxf(v.y, 0.f);
        v.z = fmaxf(v.z, 0.f); v.w = fmaxf(v.w, 0.f);
    }
    if (Xout) Xout[i] = v;
    __nv_bfloat16 h0 = __float2bfloat16(v.x);
    __nv_bfloat16 h1 = __float2bfloat16(v.y);
    __nv_bfloat16 h2 = __float2bfloat16(v.z);
    __nv_bfloat16 h3 = __float2bfloat16(v.w);
    __nv_bfloat16 l0 = __float2bfloat16(v.x - __bfloat162float(h0));
    __nv_bfloat16 l1 = __float2bfloat16(v.y - __bfloat162float(h1));
    __nv_bfloat16 l2 = __float2bfloat16(v.z - __bfloat162float(h2));
    __nv_bfloat16 l3 = __float2bfloat16(v.w - __bfloat162float(h3));
    __nv_bfloat162 hh0 = __halves2bfloat162(h0, h1);
    __nv_bfloat162 hh1 = __halves2bfloat162(h2, h3);
    __nv_bfloat162 ll0 = __halves2bfloat162(l0, l1);
    __nv_bfloat162 ll1 = __halves2bfloat162(l2, l3);
    uint2 uh, ul;
    uh.x = *(uint32_t*)&hh0; uh.y = *(uint32_t*)&hh1;
    ul.x = *(uint32_t*)&ll0; ul.y = *(uint32_t*)&ll1;
    oh[i] = uh;
    ol[i] = ul;
}

__global__ void bn_apply_v4(float4* __restrict__ X, int ld4, long total4, int relu)
{
    long i = (long)blockIdx.x * blockDim.x + threadIdx.x;
    if (i >= total4) return;
    int c = (int)(i % ld4) * 4;
    float4 v = X[i];
    v.x = (v.x - g_mean[c + 0]) * g_rstd[c + 0];
    v.y = (v.y - g_mean[c + 1]) * g_rstd[c + 1];
    v.z = (v.z - g_mean[c + 2]) * g_rstd[c + 2];
    v.w = (v.w - g_mean[c + 3]) * g_rstd[c + 3];
    if (relu) {
        v.x = fmaxf(v.x, 0.f); v.y = fmaxf(v.y, 0.f);
        v.z = fmaxf(v.z, 0.f); v.w = fmaxf(v.w, 0.f);
    }
    X[i] = v;
}

// ---------------------------------------------------------------------------
// 3. Weight transpose + bf16 hi/lo split. W: [K x N] -> out: [N x K]
// ---------------------------------------------------------------------------
__global__ void wt_conv(const float* __restrict__ W, int K, int N, int Klim,
                        __nv_bfloat16* __restrict__ oh, __nv_bfloat16* __restrict__ ol)
{
    __shared__ float t[32][33];
    int k0 = blockIdx.x * 32, n0 = blockIdx.y * 32;
    for (int i = threadIdx.y; i < 32; i += 8) {
        int k = k0 + i;
        t[i][threadIdx.x] = (k < Klim) ? W[(size_t)k * N + n0 + threadIdx.x] : 0.f;
    }
    __syncthreads();
    for (int i = threadIdx.y; i < 32; i += 8) {
        int n = n0 + i, k = k0 + threadIdx.x;
        float v = t[threadIdx.x][i];
        __nv_bfloat16 hi = __float2bfloat16(v);
        float lo = v - __bfloat162float(hi);
        oh[(size_t)n * K + k] = hi;
        ol[(size_t)n * K + k] = __float2bfloat16(lo);
    }
}

// ---------------------------------------------------------------------------
// 4. Fused cross network + cross head
// ---------------------------------------------------------------------------
__global__ __launch_bounds__(256)
void cross_kernel(const float* __restrict__ cw,
                  const float* __restrict__ cb,
                  const float* __restrict__ wout)
{
    __shared__ float x0[NF];
    __shared__ float xi[NF];
    __shared__ float red[256];
    const int row = blockIdx.x;
    const int tid = threadIdx.x;

    const float* hr = g_h + (size_t)row * LDH;
    for (int j = tid; j < NF; j += 256) {
        float v = hr[j];
        x0[j] = v; xi[j] = v;
    }
    __syncthreads();

    for (int L = 0; L < NCROSS; L++) {
        const float* w = cw + L * NF;
        float s = 0.f;
        for (int j = tid; j < NF; j += 256) s += xi[j] * w[j];
        red[tid] = s;
        __syncthreads();
        #pragma unroll
        for (int off = 128; off > 0; off >>= 1) {
            if (tid < off) red[tid] += red[tid + off];
            __syncthreads();
        }
        float dot = red[0];
        const float* b = cb + L * NF;
        for (int j = tid; j < NF; j += 256)
            xi[j] = fmaf(x0[j], dot, b[j] + xi[j]);
        __syncthreads();
    }

    float s = 0.f;
    for (int j = tid; j < NF; j += 256) s += xi[j] * wout[j];
    red[tid] = s;
    __syncthreads();
    #pragma unroll
    for (int off = 128; off > 0; off >>= 1) {
        if (tid < off) red[tid] += red[tid + off];
        __syncthreads();
    }
    if (tid == 0) g_cross_partial[row] = red[0];
}

// ---------------------------------------------------------------------------
// 5. bf16 mma.sync GEMM: C[M,N] = (Ah+Al)[M,K] @ (Bh+Bl)[N,K]^T + bias
//    3-term hi/lo, BM=BN=128, BK=32, cp.async double-buffered, ldmatrix frags.
//    Smem rows padded to 80 B (conflict-free for 8-row ldmatrix).
// ---------------------------------------------------------------------------
#define ARRSZ  (128 * 80)          // one operand tile (bf16, 80B pitch)
#define BUFSZ  (4 * ARRSZ)         // Ah, Al, Bh, Bl
#define GEMM_SMEM (2 * BUFSZ)      // 81920 B

__global__ __launch_bounds__(256, 2)
void hgemm(int K8, int nch,
           const uint4* __restrict__ Ah, const uint4* __restrict__ Al,
           const uint4* __restrict__ Bh, const uint4* __restrict__ Bl,
           const float* __restrict__ bias, float* __restrict__ C, int ldc)
{
    extern __shared__ char dsm[];
    const uint32_t sb = smem_u32(dsm);

    const int tid  = threadIdx.x;
    const int warp = tid >> 5;
    const int lane = tid & 31;
    const int wm = warp >> 2;       // 0..1
    const int wn = warp & 3;        // 0..3
    const int m0 = blockIdx.y * 128;
    const int n0 = blockIdx.x * 128;

    // ldmatrix per-lane byte offsets within an operand tile
    const uint32_t aoff = (uint32_t)(wm * 64 + (lane & 15)) * 80u
                        + ((lane >> 4) * 16u);
    const uint32_t boff = (uint32_t)(wn * 32 + ((lane >> 4) << 3) + (lane & 7)) * 80u
                        + (((lane >> 3) & 1) * 16u);

    const uint4* gb[4] = {Ah, Al, Bh, Bl};
    const int    rbase[2] = {m0, n0};

    float acc[4][4][4] = {};

    auto load_tile = [&](int ch, int buf) {
        const uint32_t bb = sb + (uint32_t)buf * BUFSZ;
        const int k0u = ch * 4;                 // 32 bf16 = 4 uint4
        #pragma unroll
        for (int i = 0; i < 8; i++) {
            const int arr = i >> 1;             // compile-time
            const int rem = ((i & 1) << 8) + tid;
            const int r = rem >> 2, c = rem & 3;
            uint32_t sa = bb + (uint32_t)arr * ARRSZ + (uint32_t)r * 80u + c * 16u;
            const uint4* gp = gb[arr] + (size_t)(rbase[arr >> 1] + r) * K8 + k0u + c;
            CP_ASYNC16(sa, gp);
        }
        CP_COMMIT();
    };

    load_tile(0, 0);

    for (int ch = 0; ch < nch; ch++) {
        CP_WAIT0();
        __syncthreads();
        if (ch + 1 < nch) load_tile(ch + 1, (ch + 1) & 1);

        const uint32_t bb = sb + (uint32_t)(ch & 1) * BUFSZ;
        #pragma unroll
        for (int ks = 0; ks < 2; ks++) {
            // B fragments: hi & lo, 4 n-tiles (two x4 loads each)
            uint32_t bh[4][2], bl[4][2];
            #pragma unroll
            for (int p = 0; p < 2; p++) {
                uint32_t ad = bb + 2 * ARRSZ + boff + (uint32_t)p * (16 * 80) + ks * 32;
                LDSM4(bh[2*p][0], bh[2*p][1], bh[2*p+1][0], bh[2*p+1][1], ad);
                ad += ARRSZ;
                LDSM4(bl[2*p][0], bl[2*p][1], bl[2*p+1][0], bl[2*p+1][1], ad);
            }
            #pragma unroll
            for (int mt = 0; mt < 4; mt++) {
                uint32_t ad = bb + aoff + (uint32_t)mt * (16 * 80) + ks * 32;
                uint32_t ah[4], al[4];
                LDSM4(ah[0], ah[1], ah[2], ah[3], ad);
                LDSM4(al[0], al[1], al[2], al[3], ad + ARRSZ);
                #pragma unroll
                for (int nt = 0; nt < 4; nt++) {
                    MMA_BF16(acc[mt][nt], ah, bh[nt]);
                    MMA_BF16(acc[mt][nt], ah, bl[nt]);
                    MMA_BF16(acc[mt][nt], al, bh[nt]);
                }
            }
        }
        __syncthreads();
    }

    // epilogue: + bias, store fp32
    const int tr = lane >> 2;
    const int tc = (lane & 3) * 2;
    #pragma unroll
    for (int mt = 0; mt < 4; mt++) {
        int row = m0 + wm * 64 + mt * 16 + tr;
        #pragma unroll
        for (int nt = 0; nt < 4; nt++) {
            int col = n0 + wn * 32 + nt * 8 + tc;
            float b0 = bias[col], b1 = bias[col + 1];
            float2 v0 = make_float2(acc[mt][nt][0] + b0, acc[mt][nt][1] + b1);
            float2 v1 = make_float2(acc[mt][nt][2] + b0, acc[mt][nt][3] + b1);
            *(float2*)(C + (size_t)row * ldc + col)       = v0;
            *(float2*)(C + (size_t)(row + 8) * ldc + col) = v1;
        }
    }
}

// ---------------------------------------------------------------------------
// 6. Final head
// ---------------------------------------------------------------------------
__global__ void final_kernel(const float* __restrict__ wout_tail,
                             float* __restrict__ out)
{
    int row  = blockIdx.x * 8 + (threadIdx.x >> 5);
    int lane = threadIdx.x & 31;
    const float* r = g_z3 + (size_t)row * N3;
    float s = 0.f;
    #pragma unroll
    for (int j = lane; j < N3; j += 32) s += r[j] * wout_tail[j];
    #pragma unroll
    for (int off = 16; off > 0; off >>= 1)
        s += __shfl_down_sync(0xffffffffu, s, off);
    if (lane == 0) {
        float z = s + g_cross_partial[row];
        out[row] = 1.0f / (1.0f + expf(-z));
    }
}

// ---------------------------------------------------------------------------
// Launcher
// ---------------------------------------------------------------------------
extern "C" void kernel_launch(void* const* d_in, const int* in_sizes, int n_in,
                              void* d_out, int out_size)
{
    const int*   sparse  = (const int*)  d_in[0];
    const float* dense   = (const float*)d_in[1];
    const float* emb_a   = (const float*)d_in[2];
    const float* emb_b   = (const float*)d_in[3];
    const float* emb_c   = (const float*)d_in[4];
    const float* cross_w = (const float*)d_in[5];
    const float* cross_b = (const float*)d_in[6];
    const float* W1      = (const float*)d_in[7];
    const float* b1      = (const float*)d_in[8];
    const float* W2      = (const float*)d_in[9];
    const float* b2      = (const float*)d_in[10];
    const float* W3      = (const float*)d_in[11];
    const float* b3      = (const float*)d_in[12];
    const float* Wout    = (const float*)d_in[13];
    float* out = (float*)d_out;

    static int smem_set = 0;
    if (!smem_set) {
        cudaFuncSetAttribute(hgemm, cudaFuncAttributeMaxDynamicSharedMemorySize, GEMM_SMEM);
        smem_set = 1;
    }

    float *ph, *pz1, *pz2, *pz3;
    cudaGetSymbolAddress((void**)&ph,  g_h);
    cudaGetSymbolAddress((void**)&pz1, g_z1);
    cudaGetSymbolAddress((void**)&pz2, g_z2);
    cudaGetSymbolAddress((void**)&pz3, g_z3);
    uint4 *pah, *pal, *pz1h, *pz1l, *pz2h, *pz2l;
    uint4 *pw1h, *pw1l, *pw2h, *pw2l, *pw3h, *pw3l;
    cudaGetSymbolAddress((void**)&pah,  g_ah);
    cudaGetSymbolAddress((void**)&pal,  g_al);
    cudaGetSymbolAddress((void**)&pz1h, g_z1h);
    cudaGetSymbolAddress((void**)&pz1l, g_z1l);
    cudaGetSymbolAddress((void**)&pz2h, g_z2h);
    cudaGetSymbolAddress((void**)&pz2l, g_z2l);
    cudaGetSymbolAddress((void**)&pw1h, g_w1h);
    cudaGetSymbolAddress((void**)&pw1l, g_w1l);
    cudaGetSymbolAddress((void**)&pw2h, g_w2h);
    cudaGetSymbolAddress((void**)&pw2l, g_w2l);
    cudaGetSymbolAddress((void**)&pw3h, g_w3h);
    cudaGetSymbolAddress((void**)&pw3l, g_w3l);

    // ---- weight transpose + bf16 split ----
    {
        dim3 blk(32, 8);
        dim3 g1(LDH / 32, N1 / 32);
        wt_conv<<<g1, blk>>>(W1, LDH, N1, NF,
                             (__nv_bfloat16*)pw1h, (__nv_bfloat16*)pw1l);
        dim3 g2(N1 / 32, N2 / 32);
        wt_conv<<<g2, blk>>>(W2, N1, N2, N1,
                             (__nv_bfloat16*)pw2h, (__nv_bfloat16*)pw2l);
        dim3 g3(N2 / 32, N3 / 32);
        wt_conv<<<g3, blk>>>(W3, N2, N3, N2,
                             (__nv_bfloat16*)pw3h, (__nv_bfloat16*)pw3l);
    }

    // ---- gather ----
    gather_kernel<<<B, 256>>>(sparse, dense, emb_a, emb_b, emb_c);

    // ---- BN(h): fp32 (for cross) + bf16 hi/lo (for GEMM1) ----
    {
        dim3 g((LDH + 127) / 128, NCHUNK);
        colstats_partial<<<g, 128>>>(ph, LDH, LDH);
        colstats_final<<<(LDH + 127) / 128, 128>>>(LDH);
        long t4 = (long)B * (LDH / 4);
        bn_apply_bf16<<<(int)((t4 + 255) / 256), 256>>>(
            (float4*)ph, (float4*)ph, (uint2*)pah, (uint2*)pal, LDH / 4, t4, 0);
    }

    // ---- cross network ----
    cross_kernel<<<B, 256>>>(cross_w, cross_b, Wout);

    // ---- layer 1 ----
    {
        dim3 grid(N1 / 128, B / 128);
        hgemm<<<grid, 256, GEMM_SMEM>>>(LDH / 8, LDH / 32, pah, pal, pw1h, pw1l, b1, pz1, N1);
        dim3 g((N1 + 127) / 128, NCHUNK);
        colstats_partial<<<g, 128>>>(pz1, N1, N1);
        colstats_final<<<(N1 + 127) / 128, 128>>>(N1);
        long t4 = (long)B * (N1 / 4);
        bn_apply_bf16<<<(int)((t4 + 255) / 256), 256>>>(
            (float4*)pz1, (float4*)nullptr, (uint2*)pz1h, (uint2*)pz1l, N1 / 4, t4, 1);
    }

    // ---- layer 2 ----
    {
        dim3 grid(N2 / 128, B / 128);
        hgemm<<<grid, 256, GEMM_SMEM>>>(N1 / 8, N1 / 32, pz1h, pz1l, pw2h, pw2l, b2, pz2, N2);
        dim3 g((N2 + 127) / 128, NCHUNK);
        colstats_partial<<<g, 128>>>(pz2, N2, N2);
        colstats_final<<<(N2 + 127) / 128, 128>>>(N2);
        long t4 = (long)B * (N2 / 4);
        bn_apply_bf16<<<(int)((t4 + 255) / 256), 256>>>(
            (float4*)pz2, (float4*)nullptr, (uint2*)pz2h, (uint2*)pz2l, N2 / 4, t4, 1);
    }

    // ---- layer 3 (fp32 out, plain BN+relu) ----
    {
        dim3 grid(N3 / 128, B / 128);
        hgemm<<<grid, 256, GEMM_SMEM>>>(N2 / 8, N2 / 32, pz2h, pz2l, pw3h, pw3l, b3, pz3, N3);
        dim3 g((N3 + 127) / 128, NCHUNK);
        colstats_partial<<<g, 128>>>(pz3, N3, N3);
        colstats_final<<<(N3 + 127) / 128, 128>>>(N3);
        long t4 = (long)B * (N3 / 4);
        bn_apply_v4<<<(int)((t4 + 255) / 256), 256>>>((float4*)pz3, N3 / 4, t4, 1);
    }

    // ---- final head ----
    final_kernel<<<B / 8, 256>>>(Wout + NF, out);
}

// round 11
// speedup vs baseline: 2.3159x; 1.2320x over previous
#include <cuda_runtime.h>
#include <cuda_bf16.h>
#include <cuda_fp16.h>
#include <math.h>
#include <stdint.h>

// ---------------------------------------------------------------------------
// Problem constants
// ---------------------------------------------------------------------------
#define B        8192
#define NF       1725          // 8*106 + 10*60 + 8*33 + 13
#define LDH      1728          // padded leading dim (div by 64)
#define N1       1024
#define N2       512
#define N3       256
#define NCROSS   4
#define EPS      1e-5f
#define NCHUNK   32
#define ROWS_PER_CHUNK (B / NCHUNK)

// ---------------------------------------------------------------------------
// Scratch (device globals; no allocation allowed)
// ---------------------------------------------------------------------------
__device__ float g_h   [B * LDH];            // fp32 normalized features (cross)
__device__ float g_z1  [B * N1];
__device__ float g_z2  [B * N2];
__device__ float g_z3  [B * N3];
__device__ float g_cross_partial[B];
__device__ float g_psum[NCHUNK * LDH];
__device__ float g_psq [NCHUNK * LDH];
__device__ float g_mean[LDH];
__device__ float g_rstd[LDH];
__device__ int4  g_tab [LDH];                // gather decode table

// fp16 activations (uint4 = 8 halves)
__device__ uint4 g_af [B * LDH / 8];
__device__ uint4 g_z1f[B * N1 / 8];
__device__ uint4 g_z2f[B * N2 / 8];
// fp16 hi/lo transposed weights (row n, K contiguous)
__device__ uint4 g_w1h[N1 * LDH / 8];
__device__ uint4 g_w1l[N1 * LDH / 8];
__device__ uint4 g_w2h[N2 * N1 / 8];
__device__ uint4 g_w2l[N2 * N1 / 8];
__device__ uint4 g_w3h[N3 * N2 / 8];
__device__ uint4 g_w3l[N3 * N2 / 8];

// ---------------------------------------------------------------------------
// PTX helpers (legacy tensor path: compute_103-safe)
// ---------------------------------------------------------------------------
__device__ __forceinline__ uint32_t smem_u32(const void* p) {
    uint32_t a;
    asm("{ .reg .u64 t; cvta.to.shared.u64 t, %1; cvt.u32.u64 %0, t; }"
        : "=r"(a) : "l"(p));
    return a;
}

#define CP_ASYNC16(saddr, gptr) \
    asm volatile("cp.async.cg.shared.global [%0], [%1], 16;" :: "r"(saddr), "l"(gptr))
#define CP_COMMIT()  asm volatile("cp.async.commit_group;" ::: "memory")
#define CP_WAIT0()   asm volatile("cp.async.wait_group 0;" ::: "memory")

#define LDSM4(r0, r1, r2, r3, addr) \
    asm volatile("ldmatrix.sync.aligned.m8n8.x4.shared.b16 {%0,%1,%2,%3}, [%4];" \
        : "=r"(r0), "=r"(r1), "=r"(r2), "=r"(r3) : "r"(addr))

#define MMA_F16(d, a, b) \
    asm volatile("mma.sync.aligned.m16n8k16.row.col.f32.f16.f16.f32 " \
        "{%0,%1,%2,%3},{%4,%5,%6,%7},{%8,%9},{%0,%1,%2,%3};" \
        : "+f"((d)[0]), "+f"((d)[1]), "+f"((d)[2]), "+f"((d)[3]) \
        : "r"((a)[0]), "r"((a)[1]), "r"((a)[2]), "r"((a)[3]),     \
          "r"((b)[0]), "r"((b)[1]))

// ---------------------------------------------------------------------------
// 0. Gather decode table (src, stride/col, elem offset, sparse field)
// ---------------------------------------------------------------------------
__global__ void build_tab()
{
    int j = blockIdx.x * 256 + threadIdx.x;
    if (j >= LDH) return;
    int4 e;
    if (j < 848) {
        int f = j / 106, c = j - f * 106;
        e = make_int4(0, 106, f * 100000 * 106 + c, f);
    } else if (j < 1448) {
        int t = j - 848;
        int f = t / 60, c = t - f * 60;
        e = make_int4(1, 60, f * 10000 * 60 + c, 8 + f);
    } else if (j < 1712) {
        int t = j - 1448;
        int f = t / 33, c = t - f * 33;
        e = make_int4(2, 33, f * 1000 * 33 + c, 18 + f);
    } else if (j < 1725) {
        e = make_int4(3, j - 1712, 0, 0);
    } else {
        e = make_int4(4, 0, 0, 0);
    }
    g_tab[j] = e;
}

// ---------------------------------------------------------------------------
// 1. Gather (table-driven, no div/mod)
// ---------------------------------------------------------------------------
__global__ void gather_kernel(const int* __restrict__ sparse,
                              const float* __restrict__ dense,
                              const float* __restrict__ emb_a,
                              const float* __restrict__ emb_b,
                              const float* __restrict__ emb_c)
{
    __shared__ int sp[26];
    const int row = blockIdx.x;
    if (threadIdx.x < 26) sp[threadIdx.x] = sparse[row * 26 + threadIdx.x];
    __syncthreads();

    float* hr = g_h + (size_t)row * LDH;
    for (int j = threadIdx.x; j < LDH; j += blockDim.x) {
        int4 e = g_tab[j];
        float v;
        if (e.x == 0)      v = emb_a[(size_t)e.z + (size_t)sp[e.w] * e.y];
        else if (e.x == 1) v = emb_b[(size_t)e.z + (size_t)sp[e.w] * e.y];
        else if (e.x == 2) v = emb_c[(size_t)e.z + (size_t)sp[e.w] * e.y];
        else if (e.x == 3) v = dense[row * 13 + e.y];
        else               v = 0.0f;
        hr[j] = v;
    }
}

// ---------------------------------------------------------------------------
// 2. Column stats + normalize
// ---------------------------------------------------------------------------
__global__ void colstats_partial(const float* __restrict__ X, int ld, int ncols)
{
    int col = blockIdx.x * blockDim.x + threadIdx.x;
    if (col >= ncols) return;
    int r0 = blockIdx.y * ROWS_PER_CHUNK;
    float s = 0.f, q = 0.f;
    const float* p = X + (size_t)r0 * ld + col;
    for (int r = 0; r < ROWS_PER_CHUNK; r++) {
        float v = p[(size_t)r * ld];
        s += v; q += v * v;
    }
    g_psum[blockIdx.y * ncols + col] = s;
    g_psq [blockIdx.y * ncols + col] = q;
}

__global__ void colstats_final(int ncols)
{
    int col = blockIdx.x * blockDim.x + threadIdx.x;
    if (col >= ncols) return;
    float s = 0.f, q = 0.f;
    for (int c = 0; c < NCHUNK; c++) {
        s += g_psum[c * ncols + col];
        q += g_psq [c * ncols + col];
    }
    float mean = s * (1.0f / B);
    float var  = q * (1.0f / B) - mean * mean;
    g_mean[col] = mean;
    g_rstd[col] = rsqrtf(var + EPS);
}

// normalize (+relu), optionally keep fp32, emit packed fp16
__global__ void bn_apply_fp16(const float4* __restrict__ X, float4* __restrict__ Xout,
                              uint2* __restrict__ ofp,
                              int ld4, long total4, int relu)
{
    long i = (long)blockIdx.x * blockDim.x + threadIdx.x;
    if (i >= total4) return;
    int c = (int)(i % ld4) * 4;
    float4 v = X[i];
    v.x = (v.x - g_mean[c + 0]) * g_rstd[c + 0];
    v.y = (v.y - g_mean[c + 1]) * g_rstd[c + 1];
    v.z = (v.z - g_mean[c + 2]) * g_rstd[c + 2];
    v.w = (v.w - g_mean[c + 3]) * g_rstd[c + 3];
    if (relu) {
        v.x = fmaxf(v.x, 0.f); v.y = fmaxf(v.y, 0.f);
        v.z = fmaxf(v.z, 0.f); v.w = fmaxf(v.w, 0.f);
    }
    if (Xout) Xout[i] = v;
    __half2 p0 = __floats2half2_rn(v.x, v.y);
    __half2 p1 = __floats2half2_rn(v.z, v.w);
    uint2 u;
    u.x = *(uint32_t*)&p0;
    u.y = *(uint32_t*)&p1;
    ofp[i] = u;
}

__global__ void bn_apply_v4(float4* __restrict__ X, int ld4, long total4, int relu)
{
    long i = (long)blockIdx.x * blockDim.x + threadIdx.x;
    if (i >= total4) return;
    int c = (int)(i % ld4) * 4;
    float4 v = X[i];
    v.x = (v.x - g_mean[c + 0]) * g_rstd[c + 0];
    v.y = (v.y - g_mean[c + 1]) * g_rstd[c + 1];
    v.z = (v.z - g_mean[c + 2]) * g_rstd[c + 2];
    v.w = (v.w - g_mean[c + 3]) * g_rstd[c + 3];
    if (relu) {
        v.x = fmaxf(v.x, 0.f); v.y = fmaxf(v.y, 0.f);
        v.z = fmaxf(v.z, 0.f); v.w = fmaxf(v.w, 0.f);
    }
    X[i] = v;
}

// ---------------------------------------------------------------------------
// 3. Weight transpose + fp16 hi/lo split. W: [K x N] -> out: [N x K]
// ---------------------------------------------------------------------------
__global__ void wt_conv(const float* __restrict__ W, int K, int N, int Klim,
                        __half* __restrict__ oh, __half* __restrict__ ol)
{
    __shared__ float t[32][33];
    int k0 = blockIdx.x * 32, n0 = blockIdx.y * 32;
    for (int i = threadIdx.y; i < 32; i += 8) {
        int k = k0 + i;
        t[i][threadIdx.x] = (k < Klim) ? W[(size_t)k * N + n0 + threadIdx.x] : 0.f;
    }
    __syncthreads();
    for (int i = threadIdx.y; i < 32; i += 8) {
        int n = n0 + i, k = k0 + threadIdx.x;
        float v = t[threadIdx.x][i];
        __half hi = __float2half_rn(v);
        float lo = v - __half2float(hi);
        oh[(size_t)n * K + k] = hi;
        ol[(size_t)n * K + k] = __float2half_rn(lo);
    }
}

// ---------------------------------------------------------------------------
// 4. Fused cross network + cross head
// ---------------------------------------------------------------------------
__global__ __launch_bounds__(256)
void cross_kernel(const float* __restrict__ cw,
                  const float* __restrict__ cb,
                  const float* __restrict__ wout)
{
    __shared__ float x0[NF];
    __shared__ float xi[NF];
    __shared__ float red[256];
    const int row = blockIdx.x;
    const int tid = threadIdx.x;

    const float* hr = g_h + (size_t)row * LDH;
    for (int j = tid; j < NF; j += 256) {
        float v = hr[j];
        x0[j] = v; xi[j] = v;
    }
    __syncthreads();

    for (int L = 0; L < NCROSS; L++) {
        const float* w = cw + L * NF;
        float s = 0.f;
        for (int j = tid; j < NF; j += 256) s += xi[j] * w[j];
        red[tid] = s;
        __syncthreads();
        #pragma unroll
        for (int off = 128; off > 0; off >>= 1) {
            if (tid < off) red[tid] += red[tid + off];
            __syncthreads();
        }
        float dot = red[0];
        const float* b = cb + L * NF;
        for (int j = tid; j < NF; j += 256)
            xi[j] = fmaf(x0[j], dot, b[j] + xi[j]);
        __syncthreads();
    }

    float s = 0.f;
    for (int j = tid; j < NF; j += 256) s += xi[j] * wout[j];
    red[tid] = s;
    __syncthreads();
    #pragma unroll
    for (int off = 128; off > 0; off >>= 1) {
        if (tid < off) red[tid] += red[tid + off];
        __syncthreads();
    }
    if (tid == 0) g_cross_partial[row] = red[0];
}

// ---------------------------------------------------------------------------
// 5. fp16 mma.sync GEMM: C[M,N] = A[M,K] @ (Bh+Bl)[N,K]^T + bias
//    2-term (weights hi/lo exact; activations fp16-rounded).
//    BM=BN=128, BK=32, cp.async double-buffered, ldmatrix frags, 80B pitch.
// ---------------------------------------------------------------------------
#define ARRSZ  (128 * 80)          // one operand tile (fp16, 80B pitch)
#define BUFSZ  (3 * ARRSZ)         // A, Bh, Bl = 30720
#define GEMM_SMEM (2 * BUFSZ)      // 61440 B

__global__ __launch_bounds__(256, 2)
void hgemm(int K8, int nch,
           const uint4* __restrict__ A,
           const uint4* __restrict__ Bh, const uint4* __restrict__ Bl,
           const float* __restrict__ bias, float* __restrict__ C, int ldc)
{
    extern __shared__ char dsm[];
    const uint32_t sb = smem_u32(dsm);

    const int tid  = threadIdx.x;
    const int warp = tid >> 5;
    const int lane = tid & 31;
    const int wm = warp >> 2;       // 0..1
    const int wn = warp & 3;        // 0..3
    const int m0 = blockIdx.y * 128;
    const int n0 = blockIdx.x * 128;

    // ldmatrix per-lane byte offsets within an operand tile
    const uint32_t aoff = (uint32_t)(wm * 64 + (lane & 15)) * 80u
                        + ((lane >> 4) * 16u);
    const uint32_t boff = (uint32_t)(wn * 32 + ((lane >> 4) << 3) + (lane & 7)) * 80u
                        + (((lane >> 3) & 1) * 16u);

    const uint4* gb[3] = {A, Bh, Bl};
    const int    rbase[3] = {m0, n0, n0};

    float acc[4][4][4] = {};

    auto load_tile = [&](int ch, int buf) {
        const uint32_t bb = sb + (uint32_t)buf * BUFSZ;
        const int k0u = ch * 4;                 // 32 fp16 = 4 uint4
        #pragma unroll
        for (int i = 0; i < 6; i++) {
            const int arr = i >> 1;             // compile-time: 0,0,1,1,2,2
            const int rem = ((i & 1) << 8) + tid;
            const int r = rem >> 2, c = rem & 3;
            uint32_t sa = bb + (uint32_t)arr * ARRSZ + (uint32_t)r * 80u + c * 16u;
            const uint4* gp = gb[arr] + (size_t)(rbase[arr] + r) * K8 + k0u + c;
            CP_ASYNC16(sa, gp);
        }
        CP_COMMIT();
    };

    load_tile(0, 0);

    for (int ch = 0; ch < nch; ch++) {
        CP_WAIT0();
        __syncthreads();
        if (ch + 1 < nch) load_tile(ch + 1, (ch + 1) & 1);

        const uint32_t bb = sb + (uint32_t)(ch & 1) * BUFSZ;
        #pragma unroll
        for (int ks = 0; ks < 2; ks++) {
            uint32_t bh[4][2], bl[4][2];
            #pragma unroll
            for (int p = 0; p < 2; p++) {
                uint32_t ad = bb + ARRSZ + boff + (uint32_t)p * (16 * 80) + ks * 32;
                LDSM4(bh[2*p][0], bh[2*p][1], bh[2*p+1][0], bh[2*p+1][1], ad);
                ad += ARRSZ;
                LDSM4(bl[2*p][0], bl[2*p][1], bl[2*p+1][0], bl[2*p+1][1], ad);
            }
            #pragma unroll
            for (int mt = 0; mt < 4; mt++) {
                uint32_t ad = bb + aoff + (uint32_t)mt * (16 * 80) + ks * 32;
                uint32_t af[4];
                LDSM4(af[0], af[1], af[2], af[3], ad);
                #pragma unroll
                for (int nt = 0; nt < 4; nt++) {
                    MMA_F16(acc[mt][nt], af, bh[nt]);
                    MMA_F16(acc[mt][nt], af, bl[nt]);
                }
            }
        }
        __syncthreads();
    }

    // epilogue: + bias, store fp32
    const int tr = lane >> 2;
    const int tc = (lane & 3) * 2;
    #pragma unroll
    for (int mt = 0; mt < 4; mt++) {
        int row = m0 + wm * 64 + mt * 16 + tr;
        #pragma unroll
        for (int nt = 0; nt < 4; nt++) {
            int col = n0 + wn * 32 + nt * 8 + tc;
            float b0 = bias[col], b1 = bias[col + 1];
            float2 v0 = make_float2(acc[mt][nt][0] + b0, acc[mt][nt][1] + b1);
            float2 v1 = make_float2(acc[mt][nt][2] + b0, acc[mt][nt][3] + b1);
            *(float2*)(C + (size_t)row * ldc + col)       = v0;
            *(float2*)(C + (size_t)(row + 8) * ldc + col) = v1;
        }
    }
}

// ---------------------------------------------------------------------------
// 6. Final head
// ---------------------------------------------------------------------------
__global__ void final_kernel(const float* __restrict__ wout_tail,
                             float* __restrict__ out)
{
    int row  = blockIdx.x * 8 + (threadIdx.x >> 5);
    int lane = threadIdx.x & 31;
    const float* r = g_z3 + (size_t)row * N3;
    float s = 0.f;
    #pragma unroll
    for (int j = lane; j < N3; j += 32) s += r[j] * wout_tail[j];
    #pragma unroll
    for (int off = 16; off > 0; off >>= 1)
        s += __shfl_down_sync(0xffffffffu, s, off);
    if (lane == 0) {
        float z = s + g_cross_partial[row];
        out[row] = 1.0f / (1.0f + expf(-z));
    }
}

// ---------------------------------------------------------------------------
// Launcher
// ---------------------------------------------------------------------------
extern "C" void kernel_launch(void* const* d_in, const int* in_sizes, int n_in,
                              void* d_out, int out_size)
{
    const int*   sparse  = (const int*)  d_in[0];
    const float* dense   = (const float*)d_in[1];
    const float* emb_a   = (const float*)d_in[2];
    const float* emb_b   = (const float*)d_in[3];
    const float* emb_c   = (const float*)d_in[4];
    const float* cross_w = (const float*)d_in[5];
    const float* cross_b = (const float*)d_in[6];
    const float* W1      = (const float*)d_in[7];
    const float* b1      = (const float*)d_in[8];
    const float* W2      = (const float*)d_in[9];
    const float* b2      = (const float*)d_in[10];
    const float* W3      = (const float*)d_in[11];
    const float* b3      = (const float*)d_in[12];
    const float* Wout    = (const float*)d_in[13];
    float* out = (float*)d_out;

    static int smem_set = 0;
    if (!smem_set) {
        cudaFuncSetAttribute(hgemm, cudaFuncAttributeMaxDynamicSharedMemorySize, GEMM_SMEM);
        smem_set = 1;
    }

    float *ph, *pz1, *pz2, *pz3;
    cudaGetSymbolAddress((void**)&ph,  g_h);
    cudaGetSymbolAddress((void**)&pz1, g_z1);
    cudaGetSymbolAddress((void**)&pz2, g_z2);
    cudaGetSymbolAddress((void**)&pz3, g_z3);
    uint4 *paf, *pz1f, *pz2f;
    uint4 *pw1h, *pw1l, *pw2h, *pw2l, *pw3h, *pw3l;
    cudaGetSymbolAddress((void**)&paf,  g_af);
    cudaGetSymbolAddress((void**)&pz1f, g_z1f);
    cudaGetSymbolAddress((void**)&pz2f, g_z2f);
    cudaGetSymbolAddress((void**)&pw1h, g_w1h);
    cudaGetSymbolAddress((void**)&pw1l, g_w1l);
    cudaGetSymbolAddress((void**)&pw2h, g_w2h);
    cudaGetSymbolAddress((void**)&pw2l, g_w2l);
    cudaGetSymbolAddress((void**)&pw3h, g_w3h);
    cudaGetSymbolAddress((void**)&pw3l, g_w3l);

    // ---- decode table + weight transpose/split ----
    build_tab<<<(LDH + 255) / 256, 256>>>();
    {
        dim3 blk(32, 8);
        dim3 g1(LDH / 32, N1 / 32);
        wt_conv<<<g1, blk>>>(W1, LDH, N1, NF, (__half*)pw1h, (__half*)pw1l);
        dim3 g2(N1 / 32, N2 / 32);
        wt_conv<<<g2, blk>>>(W2, N1, N2, N1, (__half*)pw2h, (__half*)pw2l);
        dim3 g3(N2 / 32, N3 / 32);
        wt_conv<<<g3, blk>>>(W3, N2, N3, N2, (__half*)pw3h, (__half*)pw3l);
    }

    // ---- gather ----
    gather_kernel<<<B, 256>>>(sparse, dense, emb_a, emb_b, emb_c);

    // ---- BN(h): fp32 (for cross) + fp16 (for GEMM1) ----
    {
        dim3 g((LDH + 127) / 128, NCHUNK);
        colstats_partial<<<g, 128>>>(ph, LDH, LDH);
        colstats_final<<<(LDH + 127) / 128, 128>>>(LDH);
        long t4 = (long)B * (LDH / 4);
        bn_apply_fp16<<<(int)((t4 + 255) / 256), 256>>>(
            (float4*)ph, (float4*)ph, (uint2*)paf, LDH / 4, t4, 0);
    }

    // ---- cross network ----
    cross_kernel<<<B, 256>>>(cross_w, cross_b, Wout);

    // ---- layer 1 ----
    {
        dim3 grid(N1 / 128, B / 128);
        hgemm<<<grid, 256, GEMM_SMEM>>>(LDH / 8, LDH / 32, paf, pw1h, pw1l, b1, pz1, N1);
        dim3 g((N1 + 127) / 128, NCHUNK);
        colstats_partial<<<g, 128>>>(pz1, N1, N1);
        colstats_final<<<(N1 + 127) / 128, 128>>>(N1);
        long t4 = (long)B * (N1 / 4);
        bn_apply_fp16<<<(int)((t4 + 255) / 256), 256>>>(
            (float4*)pz1, (float4*)nullptr, (uint2*)pz1f, N1 / 4, t4, 1);
    }

    // ---- layer 2 ----
    {
        dim3 grid(N2 / 128, B / 128);
        hgemm<<<grid, 256, GEMM_SMEM>>>(N1 / 8, N1 / 32, pz1f, pw2h, pw2l, b2, pz2, N2);
        dim3 g((N2 + 127) / 128, NCHUNK);
        colstats_partial<<<g, 128>>>(pz2, N2, N2);
        colstats_final<<<(N2 + 127) / 128, 128>>>(N2);
        long t4 = (long)B * (N2 / 4);
        bn_apply_fp16<<<(int)((t4 + 255) / 256), 256>>>(
            (float4*)pz2, (float4*)nullptr, (uint2*)pz2f, N2 / 4, t4, 1);
    }

    // ---- layer 3 (fp32 out, plain BN+relu) ----
    {
        dim3 grid(N3 / 128, B / 128);
        hgemm<<<grid, 256, GEMM_SMEM>>>(N2 / 8, N2 / 32, pz2f, pw3h, pw3l, b3, pz3, N3);
        dim3 g((N3 + 127) / 128, NCHUNK);
        colstats_partial<<<g, 128>>>(pz3, N3, N3);
        colstats_final<<<(N3 + 127) / 128, 128>>>(N3);
        long t4 = (long)B * (N3 / 4);
        bn_apply_v4<<<(int)((t4 + 255) / 256), 256>>>((float4*)pz3, N3 / 4, t4, 1);
    }

    // ---- final head ----
    final_kernel<<<B / 8, 256>>>(Wout + NF, out);
}

// round 12
// speedup vs baseline: 3.0845x; 1.3319x over previous
#include <cuda_runtime.h>
#include <cuda_bf16.h>
#include <cuda_fp16.h>
#include <math.h>
#include <stdint.h>

// ---------------------------------------------------------------------------
// Problem constants
// ---------------------------------------------------------------------------
#define B        8192
#define NF       1725          // 8*106 + 10*60 + 8*33 + 13
#define LDH      1728          // padded leading dim (div by 64)
#define N1       1024
#define N2       512
#define N3       256
#define NCROSS   4
#define EPS      1e-5f
#define NCHUNK   32            // row chunks for h column stats
#define ROWS_PER_CHUNK (B / NCHUNK)
#define GCHUNK   64            // row chunks for GEMM-fused stats (B/128)

// ---------------------------------------------------------------------------
// Scratch (device globals; no allocation allowed)
// ---------------------------------------------------------------------------
__device__ float g_h   [B * LDH];            // fp32 normalized features (cross)
__device__ float g_z1  [B * N1];
__device__ float g_z2  [B * N2];
__device__ float g_z3  [B * N3];
__device__ float g_cross_partial[B];
__device__ float g_psum[GCHUNK * LDH];
__device__ float g_psq [GCHUNK * LDH];
__device__ float g_mean[LDH];
__device__ float g_rstd[LDH];
__device__ int4  g_tab [LDH];                // gather decode table

// fp16 activations (uint4 = 8 halves)
__device__ uint4 g_af [B * LDH / 8];
__device__ uint4 g_z1f[B * N1 / 8];
__device__ uint4 g_z2f[B * N2 / 8];
// fp16 transposed weights (row n, K contiguous)
__device__ uint4 g_w1f[N1 * LDH / 8];
__device__ uint4 g_w2f[N2 * N1 / 8];
__device__ uint4 g_w3f[N3 * N2 / 8];

// ---------------------------------------------------------------------------
// PTX helpers (legacy tensor path: compute_103-safe)
// ---------------------------------------------------------------------------
__device__ __forceinline__ uint32_t smem_u32(const void* p) {
    uint32_t a;
    asm("{ .reg .u64 t; cvta.to.shared.u64 t, %1; cvt.u32.u64 %0, t; }"
        : "=r"(a) : "l"(p));
    return a;
}

#define CP_ASYNC16(saddr, gptr) \
    asm volatile("cp.async.cg.shared.global [%0], [%1], 16;" :: "r"(saddr), "l"(gptr))
#define CP_COMMIT()  asm volatile("cp.async.commit_group;" ::: "memory")
#define CP_WAIT1()   asm volatile("cp.async.wait_group 1;" ::: "memory")

#define LDSM4(r0, r1, r2, r3, addr) \
    asm volatile("ldmatrix.sync.aligned.m8n8.x4.shared.b16 {%0,%1,%2,%3}, [%4];" \
        : "=r"(r0), "=r"(r1), "=r"(r2), "=r"(r3) : "r"(addr))

#define MMA_F16(d, a, b) \
    asm volatile("mma.sync.aligned.m16n8k16.row.col.f32.f16.f16.f32 " \
        "{%0,%1,%2,%3},{%4,%5,%6,%7},{%8,%9},{%0,%1,%2,%3};" \
        : "+f"((d)[0]), "+f"((d)[1]), "+f"((d)[2]), "+f"((d)[3]) \
        : "r"((a)[0]), "r"((a)[1]), "r"((a)[2]), "r"((a)[3]),     \
          "r"((b)[0]), "r"((b)[1]))

// ---------------------------------------------------------------------------
// 0. Gather decode table (src, stride/col, elem offset, sparse field)
// ---------------------------------------------------------------------------
__global__ void build_tab()
{
    int j = blockIdx.x * 256 + threadIdx.x;
    if (j >= LDH) return;
    int4 e;
    if (j < 848) {
        int f = j / 106, c = j - f * 106;
        e = make_int4(0, 106, f * 100000 * 106 + c, f);
    } else if (j < 1448) {
        int t = j - 848;
        int f = t / 60, c = t - f * 60;
        e = make_int4(1, 60, f * 10000 * 60 + c, 8 + f);
    } else if (j < 1712) {
        int t = j - 1448;
        int f = t / 33, c = t - f * 33;
        e = make_int4(2, 33, f * 1000 * 33 + c, 18 + f);
    } else if (j < 1725) {
        e = make_int4(3, j - 1712, 0, 0);
    } else {
        e = make_int4(4, 0, 0, 0);
    }
    g_tab[j] = e;
}

// ---------------------------------------------------------------------------
// 1. Gather (table-driven)
// ---------------------------------------------------------------------------
__global__ void gather_kernel(const int* __restrict__ sparse,
                              const float* __restrict__ dense,
                              const float* __restrict__ emb_a,
                              const float* __restrict__ emb_b,
                              const float* __restrict__ emb_c)
{
    __shared__ int sp[26];
    const int row = blockIdx.x;
    if (threadIdx.x < 26) sp[threadIdx.x] = sparse[row * 26 + threadIdx.x];
    __syncthreads();

    float* hr = g_h + (size_t)row * LDH;
    for (int j = threadIdx.x; j < LDH; j += blockDim.x) {
        int4 e = g_tab[j];
        float v;
        if (e.x == 0)      v = emb_a[(size_t)e.z + (size_t)sp[e.w] * e.y];
        else if (e.x == 1) v = emb_b[(size_t)e.z + (size_t)sp[e.w] * e.y];
        else if (e.x == 2) v = emb_c[(size_t)e.z + (size_t)sp[e.w] * e.y];
        else if (e.x == 3) v = dense[row * 13 + e.y];
        else               v = 0.0f;
        hr[j] = v;
    }
}

// ---------------------------------------------------------------------------
// 2. Column stats + normalize
// ---------------------------------------------------------------------------
__global__ void colstats_partial(const float* __restrict__ X, int ld, int ncols)
{
    int col = blockIdx.x * blockDim.x + threadIdx.x;
    if (col >= ncols) return;
    int r0 = blockIdx.y * ROWS_PER_CHUNK;
    float s = 0.f, q = 0.f;
    const float* p = X + (size_t)r0 * ld + col;
    for (int r = 0; r < ROWS_PER_CHUNK; r++) {
        float v = p[(size_t)r * ld];
        s += v; q += v * v;
    }
    g_psum[blockIdx.y * ncols + col] = s;
    g_psq [blockIdx.y * ncols + col] = q;
}

__global__ void colstats_final(int ncols, int nchunks)
{
    int col = blockIdx.x * blockDim.x + threadIdx.x;
    if (col >= ncols) return;
    float s = 0.f, q = 0.f;
    for (int c = 0; c < nchunks; c++) {
        s += g_psum[c * ncols + col];
        q += g_psq [c * ncols + col];
    }
    float mean = s * (1.0f / B);
    float var  = q * (1.0f / B) - mean * mean;
    g_mean[col] = mean;
    g_rstd[col] = rsqrtf(var + EPS);
}

// normalize (+relu), optionally keep fp32, emit packed fp16
__global__ void bn_apply_fp16(const float4* __restrict__ X, float4* __restrict__ Xout,
                              uint2* __restrict__ ofp,
                              int ld4, long total4, int relu)
{
    long i = (long)blockIdx.x * blockDim.x + threadIdx.x;
    if (i >= total4) return;
    int c = (int)(i % ld4) * 4;
    float4 v = X[i];
    v.x = (v.x - g_mean[c + 0]) * g_rstd[c + 0];
    v.y = (v.y - g_mean[c + 1]) * g_rstd[c + 1];
    v.z = (v.z - g_mean[c + 2]) * g_rstd[c + 2];
    v.w = (v.w - g_mean[c + 3]) * g_rstd[c + 3];
    if (relu) {
        v.x = fmaxf(v.x, 0.f); v.y = fmaxf(v.y, 0.f);
        v.z = fmaxf(v.z, 0.f); v.w = fmaxf(v.w, 0.f);
    }
    if (Xout) Xout[i] = v;
    __half2 p0 = __floats2half2_rn(v.x, v.y);
    __half2 p1 = __floats2half2_rn(v.z, v.w);
    uint2 u;
    u.x = *(uint32_t*)&p0;
    u.y = *(uint32_t*)&p1;
    ofp[i] = u;
}

__global__ void bn_apply_v4(float4* __restrict__ X, int ld4, long total4, int relu)
{
    long i = (long)blockIdx.x * blockDim.x + threadIdx.x;
    if (i >= total4) return;
    int c = (int)(i % ld4) * 4;
    float4 v = X[i];
    v.x = (v.x - g_mean[c + 0]) * g_rstd[c + 0];
    v.y = (v.y - g_mean[c + 1]) * g_rstd[c + 1];
    v.z = (v.z - g_mean[c + 2]) * g_rstd[c + 2];
    v.w = (v.w - g_mean[c + 3]) * g_rstd[c + 3];
    if (relu) {
        v.x = fmaxf(v.x, 0.f); v.y = fmaxf(v.y, 0.f);
        v.z = fmaxf(v.z, 0.f); v.w = fmaxf(v.w, 0.f);
    }
    X[i] = v;
}

// ---------------------------------------------------------------------------
// 3. Weight transpose + fp16 convert. W: [K x N] -> out: [N x K]
// ---------------------------------------------------------------------------
__global__ void wt_conv(const float* __restrict__ W, int K, int N, int Klim,
                        __half* __restrict__ of)
{
    __shared__ float t[32][33];
    int k0 = blockIdx.x * 32, n0 = blockIdx.y * 32;
    for (int i = threadIdx.y; i < 32; i += 8) {
        int k = k0 + i;
        t[i][threadIdx.x] = (k < Klim) ? W[(size_t)k * N + n0 + threadIdx.x] : 0.f;
    }
    __syncthreads();
    for (int i = threadIdx.y; i < 32; i += 8) {
        int n = n0 + i, k = k0 + threadIdx.x;
        of[(size_t)n * K + k] = __float2half_rn(t[threadIdx.x][i]);
    }
}

// ---------------------------------------------------------------------------
// 4. Fused cross network + cross head
// ---------------------------------------------------------------------------
__global__ __launch_bounds__(256)
void cross_kernel(const float* __restrict__ cw,
                  const float* __restrict__ cb,
                  const float* __restrict__ wout)
{
    __shared__ float x0[NF];
    __shared__ float xi[NF];
    __shared__ float red[256];
    const int row = blockIdx.x;
    const int tid = threadIdx.x;

    const float* hr = g_h + (size_t)row * LDH;
    for (int j = tid; j < NF; j += 256) {
        float v = hr[j];
        x0[j] = v; xi[j] = v;
    }
    __syncthreads();

    for (int L = 0; L < NCROSS; L++) {
        const float* w = cw + L * NF;
        float s = 0.f;
        for (int j = tid; j < NF; j += 256) s += xi[j] * w[j];
        red[tid] = s;
        __syncthreads();
        #pragma unroll
        for (int off = 128; off > 0; off >>= 1) {
            if (tid < off) red[tid] += red[tid + off];
            __syncthreads();
        }
        float dot = red[0];
        const float* b = cb + L * NF;
        for (int j = tid; j < NF; j += 256)
            xi[j] = fmaf(x0[j], dot, b[j] + xi[j]);
        __syncthreads();
    }

    float s = 0.f;
    for (int j = tid; j < NF; j += 256) s += xi[j] * wout[j];
    red[tid] = s;
    __syncthreads();
    #pragma unroll
    for (int off = 128; off > 0; off >>= 1) {
        if (tid < off) red[tid] += red[tid + off];
        __syncthreads();
    }
    if (tid == 0) g_cross_partial[row] = red[0];
}

// ---------------------------------------------------------------------------
// 5. fp16 mma.sync GEMM + bias + fused column stats.
//    C[M,N] = A[M,K] @ B[N,K]^T + bias;  per-CTA column sums -> g_psum/g_psq.
//    BM=BN=128, BK=32, 3-stage cp.async pipeline, ldmatrix, 80B pitch.
// ---------------------------------------------------------------------------
#define ARRSZ  (128 * 80)          // one operand tile (fp16, 80B pitch)
#define BUFSZ  (2 * ARRSZ)         // A, B = 20480
#define NSTAGE 3
#define GEMM_SMEM (NSTAGE * BUFSZ) // 61440 B

__global__ __launch_bounds__(256, 2)
void hgemm(int K8, int nch,
           const uint4* __restrict__ A, const uint4* __restrict__ Bm,
           const float* __restrict__ bias, float* __restrict__ C, int ldc)
{
    extern __shared__ char dsm[];
    const uint32_t sb = smem_u32(dsm);

    const int tid  = threadIdx.x;
    const int warp = tid >> 5;
    const int lane = tid & 31;
    const int wm = warp >> 2;       // 0..1
    const int wn = warp & 3;        // 0..3
    const int m0 = blockIdx.y * 128;
    const int n0 = blockIdx.x * 128;

    // ldmatrix per-lane byte offsets within an operand tile
    const uint32_t aoff = (uint32_t)(wm * 64 + (lane & 15)) * 80u
                        + ((lane >> 4) * 16u);
    const uint32_t boff = (uint32_t)(wn * 32 + ((lane >> 4) << 3) + (lane & 7)) * 80u
                        + (((lane >> 3) & 1) * 16u);

    float acc[4][4][4] = {};

    auto load_tile = [&](int ch, int buf) {
        const uint32_t bb = sb + (uint32_t)buf * BUFSZ;
        const int k0u = ch * 4;                 // 32 fp16 = 4 uint4
        #pragma unroll
        for (int i = 0; i < 4; i++) {
            const int rem = ((i & 1) << 8) + tid;
            const int r = rem >> 2, c = rem & 3;
            uint32_t sa = bb + (uint32_t)((i >> 1) * ARRSZ) + (uint32_t)r * 80u + c * 16u;
            const uint4* gp = (i < 2 ? A + (size_t)(m0 + r) * K8
                                     : Bm + (size_t)(n0 + r) * K8) + k0u + c;
            CP_ASYNC16(sa, gp);
        }
        CP_COMMIT();
    };

    load_tile(0, 0);
    load_tile(1, 1);

    for (int ch = 0; ch < nch; ch++) {
        CP_WAIT1();
        __syncthreads();
        if (ch + 2 < nch) load_tile(ch + 2, (ch + 2) % NSTAGE);
        else              CP_COMMIT();         // keep one group per iteration

        const uint32_t bb = sb + (uint32_t)(ch % NSTAGE) * BUFSZ;
        #pragma unroll
        for (int ks = 0; ks < 2; ks++) {
            uint32_t bh[4][2];
            #pragma unroll
            for (int p = 0; p < 2; p++) {
                uint32_t ad = bb + ARRSZ + boff + (uint32_t)p * (16 * 80) + ks * 32;
                LDSM4(bh[2*p][0], bh[2*p][1], bh[2*p+1][0], bh[2*p+1][1], ad);
            }
            #pragma unroll
            for (int mt = 0; mt < 4; mt++) {
                uint32_t ad = bb + aoff + (uint32_t)mt * (16 * 80) + ks * 32;
                uint32_t af[4];
                LDSM4(af[0], af[1], af[2], af[3], ad);
                #pragma unroll
                for (int nt = 0; nt < 4; nt++)
                    MMA_F16(acc[mt][nt], af, bh[nt]);
            }
        }
        __syncthreads();
    }

    // ---- epilogue: + bias, store, column sums/sqsums ----
    const int tr = lane >> 2;
    const int tc = (lane & 3) * 2;
    float cs[4][2] = {}, cq[4][2] = {};

    #pragma unroll
    for (int mt = 0; mt < 4; mt++) {
        int row = m0 + wm * 64 + mt * 16 + tr;
        #pragma unroll
        for (int nt = 0; nt < 4; nt++) {
            int col = n0 + wn * 32 + nt * 8 + tc;
            float b0 = bias[col], b1 = bias[col + 1];
            float a0 = acc[mt][nt][0] + b0;
            float a1 = acc[mt][nt][1] + b1;
            float a2 = acc[mt][nt][2] + b0;
            float a3 = acc[mt][nt][3] + b1;
            *(float2*)(C + (size_t)row * ldc + col)       = make_float2(a0, a1);
            *(float2*)(C + (size_t)(row + 8) * ldc + col) = make_float2(a2, a3);
            cs[nt][0] += a0 + a2;  cq[nt][0] += a0 * a0 + a2 * a2;
            cs[nt][1] += a1 + a3;  cq[nt][1] += a1 * a1 + a3 * a3;
        }
    }
    // reduce over the 8 row-lanes (bits 2..4 of lane)
    #pragma unroll
    for (int off = 4; off <= 16; off <<= 1) {
        #pragma unroll
        for (int nt = 0; nt < 4; nt++) {
            cs[nt][0] += __shfl_xor_sync(0xffffffffu, cs[nt][0], off);
            cs[nt][1] += __shfl_xor_sync(0xffffffffu, cs[nt][1], off);
            cq[nt][0] += __shfl_xor_sync(0xffffffffu, cq[nt][0], off);
            cq[nt][1] += __shfl_xor_sync(0xffffffffu, cq[nt][1], off);
        }
    }
    // combine the two row-warps (wm) via smem overlay, then write chunk stats
    float* cr = (float*)dsm;   // [wm][s/q][128] = 1024 floats
    __syncthreads();           // tiles no longer needed
    if (tr == 0) {             // lanes 0..3 hold the warp totals
        #pragma unroll
        for (int nt = 0; nt < 4; nt++) {
            int col = wn * 32 + nt * 8 + tc;
            cr[(wm * 2 + 0) * 128 + col]     = cs[nt][0];
            cr[(wm * 2 + 0) * 128 + col + 1] = cs[nt][1];
            cr[(wm * 2 + 1) * 128 + col]     = cq[nt][0];
            cr[(wm * 2 + 1) * 128 + col + 1] = cq[nt][1];
        }
    }
    __syncthreads();
    if (tid < 128) {
        float s = cr[tid] + cr[256 + tid];
        float q = cr[128 + tid] + cr[384 + tid];
        g_psum[blockIdx.y * ldc + n0 + tid] = s;
        g_psq [blockIdx.y * ldc + n0 + tid] = q;
    }
}

// ---------------------------------------------------------------------------
// 6. Final head
// ---------------------------------------------------------------------------
__global__ void final_kernel(const float* __restrict__ wout_tail,
                             float* __restrict__ out)
{
    int row  = blockIdx.x * 8 + (threadIdx.x >> 5);
    int lane = threadIdx.x & 31;
    const float* r = g_z3 + (size_t)row * N3;
    float s = 0.f;
    #pragma unroll
    for (int j = lane; j < N3; j += 32) s += r[j] * wout_tail[j];
    #pragma unroll
    for (int off = 16; off > 0; off >>= 1)
        s += __shfl_down_sync(0xffffffffu, s, off);
    if (lane == 0) {
        float z = s + g_cross_partial[row];
        out[row] = 1.0f / (1.0f + expf(-z));
    }
}

// ---------------------------------------------------------------------------
// Launcher
// ---------------------------------------------------------------------------
extern "C" void kernel_launch(void* const* d_in, const int* in_sizes, int n_in,
                              void* d_out, int out_size)
{
    const int*   sparse  = (const int*)  d_in[0];
    const float* dense   = (const float*)d_in[1];
    const float* emb_a   = (const float*)d_in[2];
    const float* emb_b   = (const float*)d_in[3];
    const float* emb_c   = (const float*)d_in[4];
    const float* cross_w = (const float*)d_in[5];
    const float* cross_b = (const float*)d_in[6];
    const float* W1      = (const float*)d_in[7];
    const float* b1      = (const float*)d_in[8];
    const float* W2      = (const float*)d_in[9];
    const float* b2      = (const float*)d_in[10];
    const float* W3      = (const float*)d_in[11];
    const float* b3      = (const float*)d_in[12];
    const float* Wout    = (const float*)d_in[13];
    float* out = (float*)d_out;

    static int smem_set = 0;
    if (!smem_set) {
        cudaFuncSetAttribute(hgemm, cudaFuncAttributeMaxDynamicSharedMemorySize, GEMM_SMEM);
        smem_set = 1;
    }

    float *ph, *pz1, *pz2, *pz3;
    cudaGetSymbolAddress((void**)&ph,  g_h);
    cudaGetSymbolAddress((void**)&pz1, g_z1);
    cudaGetSymbolAddress((void**)&pz2, g_z2);
    cudaGetSymbolAddress((void**)&pz3, g_z3);
    uint4 *paf, *pz1f, *pz2f, *pw1f, *pw2f, *pw3f;
    cudaGetSymbolAddress((void**)&paf,  g_af);
    cudaGetSymbolAddress((void**)&pz1f, g_z1f);
    cudaGetSymbolAddress((void**)&pz2f, g_z2f);
    cudaGetSymbolAddress((void**)&pw1f, g_w1f);
    cudaGetSymbolAddress((void**)&pw2f, g_w2f);
    cudaGetSymbolAddress((void**)&pw3f, g_w3f);

    // ---- decode table + weight transpose/convert ----
    build_tab<<<(LDH + 255) / 256, 256>>>();
    {
        dim3 blk(32, 8);
        dim3 g1(LDH / 32, N1 / 32);
        wt_conv<<<g1, blk>>>(W1, LDH, N1, NF, (__half*)pw1f);
        dim3 g2(N1 / 32, N2 / 32);
        wt_conv<<<g2, blk>>>(W2, N1, N2, N1, (__half*)pw2f);
        dim3 g3(N2 / 32, N3 / 32);
        wt_conv<<<g3, blk>>>(W3, N2, N3, N2, (__half*)pw3f);
    }

    // ---- gather ----
    gather_kernel<<<B, 256>>>(sparse, dense, emb_a, emb_b, emb_c);

    // ---- BN(h): fp32 (for cross) + fp16 (for GEMM1) ----
    {
        dim3 g((LDH + 127) / 128, NCHUNK);
        colstats_partial<<<g, 128>>>(ph, LDH, LDH);
        colstats_final<<<(LDH + 127) / 128, 128>>>(LDH, NCHUNK);
        long t4 = (long)B * (LDH / 4);
        bn_apply_fp16<<<(int)((t4 + 255) / 256), 256>>>(
            (float4*)ph, (float4*)ph, (uint2*)paf, LDH / 4, t4, 0);
    }

    // ---- cross network ----
    cross_kernel<<<B, 256>>>(cross_w, cross_b, Wout);

    // ---- layer 1 (GEMM w/ fused stats) ----
    {
        dim3 grid(N1 / 128, B / 128);
        hgemm<<<grid, 256, GEMM_SMEM>>>(LDH / 8, LDH / 32, paf, pw1f, b1, pz1, N1);
        colstats_final<<<(N1 + 127) / 128, 128>>>(N1, GCHUNK);
        long t4 = (long)B * (N1 / 4);
        bn_apply_fp16<<<(int)((t4 + 255) / 256), 256>>>(
            (float4*)pz1, (float4*)nullptr, (uint2*)pz1f, N1 / 4, t4, 1);
    }

    // ---- layer 2 ----
    {
        dim3 grid(N2 / 128, B / 128);
        hgemm<<<grid, 256, GEMM_SMEM>>>(N1 / 8, N1 / 32, pz1f, pw2f, b2, pz2, N2);
        colstats_final<<<(N2 + 127) / 128, 128>>>(N2, GCHUNK);
        long t4 = (long)B * (N2 / 4);
        bn_apply_fp16<<<(int)((t4 + 255) / 256), 256>>>(
            (float4*)pz2, (float4*)nullptr, (uint2*)pz2f, N2 / 4, t4, 1);
    }

    // ---- layer 3 (fp32 out, plain BN+relu) ----
    {
        dim3 grid(N3 / 128, B / 128);
        hgemm<<<grid, 256, GEMM_SMEM>>>(N2 / 8, N2 / 32, pz2f, pw3f, b3, pz3, N3);
        colstats_final<<<(N3 + 127) / 128, 128>>>(N3, GCHUNK);
        long t4 = (long)B * (N3 / 4);
        bn_apply_v4<<<(int)((t4 + 255) / 256), 256>>>((float4*)pz3, N3 / 4, t4, 1);
    }

    // ---- final head ----
    final_kernel<<<B / 8, 256>>>(Wout + NF, out);
}

// round 17
// speedup vs baseline: 3.5713x; 1.1578x over previous
#include <cuda_runtime.h>
#include <cuda_bf16.h>
#include <cuda_fp16.h>
#include <math.h>
#include <stdint.h>

// ---------------------------------------------------------------------------
// Problem constants
// ---------------------------------------------------------------------------
#define B        8192
#define NF       1725          // 8*106 + 10*60 + 8*33 + 13
#define LDH      1728          // padded leading dim (div by 64)
#define N1       1024
#define N2       512
#define N3       256
#define NCROSS   4
#define EPS      1e-5f
#define NCHUNK   32            // row chunks for h column stats
#define ROWS_PER_CHUNK (B / NCHUNK)
#define GCHUNK   64            // row chunks for GEMM-fused stats (B/128)

// ---------------------------------------------------------------------------
// Scratch (device globals; no allocation allowed)
// ---------------------------------------------------------------------------
__device__ float g_h   [B * LDH];            // fp32 normalized features (cross)
__device__ float g_z1  [B * N1];
__device__ float g_z2  [B * N2];
__device__ float g_z3  [B * N3];
__device__ float g_cross_partial[B];
__device__ float g_psum[GCHUNK * LDH];
__device__ float g_psq [GCHUNK * LDH];
__device__ int4  g_tab [LDH];                // gather decode table

// fp16 activations (uint4 = 8 halves)
__device__ uint4 g_af [B * LDH / 8];
__device__ uint4 g_z1f[B * N1 / 8];
__device__ uint4 g_z2f[B * N2 / 8];
// fp16 transposed weights (row n, K contiguous)
__device__ uint4 g_w1f[N1 * LDH / 8];
__device__ uint4 g_w2f[N2 * N1 / 8];
__device__ uint4 g_w3f[N3 * N2 / 8];

// ---------------------------------------------------------------------------
// PTX helpers (legacy tensor path: compute_103-safe)
// ---------------------------------------------------------------------------
__device__ __forceinline__ uint32_t smem_u32(const void* p) {
    uint32_t a;
    asm("{ .reg .u64 t; cvta.to.shared.u64 t, %1; cvt.u32.u64 %0, t; }"
        : "=r"(a) : "l"(p));
    return a;
}

#define CP_ASYNC16(saddr, gptr) \
    asm volatile("cp.async.cg.shared.global [%0], [%1], 16;" :: "r"(saddr), "l"(gptr))
#define CP_COMMIT()  asm volatile("cp.async.commit_group;" ::: "memory")
#define CP_WAIT2()   asm volatile("cp.async.wait_group 2;" ::: "memory")

#define LDSM4(r0, r1, r2, r3, addr) \
    asm volatile("ldmatrix.sync.aligned.m8n8.x4.shared.b16 {%0,%1,%2,%3}, [%4];" \
        : "=r"(r0), "=r"(r1), "=r"(r2), "=r"(r3) : "r"(addr))

#define MMA_F16(d, a, b) \
    asm volatile("mma.sync.aligned.m16n8k16.row.col.f32.f16.f16.f32 " \
        "{%0,%1,%2,%3},{%4,%5,%6,%7},{%8,%9},{%0,%1,%2,%3};" \
        : "+f"((d)[0]), "+f"((d)[1]), "+f"((d)[2]), "+f"((d)[3]) \
        : "r"((a)[0]), "r"((a)[1]), "r"((a)[2]), "r"((a)[3]),     \
          "r"((b)[0]), "r"((b)[1]))

// ---------------------------------------------------------------------------
// 0. Gather decode table
// ---------------------------------------------------------------------------
__global__ void build_tab()
{
    int j = blockIdx.x * 256 + threadIdx.x;
    if (j >= LDH) return;
    int4 e;
    if (j < 848) {
        int f = j / 106, c = j - f * 106;
        e = make_int4(0, 106, f * 100000 * 106 + c, f);
    } else if (j < 1448) {
        int t = j - 848;
        int f = t / 60, c = t - f * 60;
        e = make_int4(1, 60, f * 10000 * 60 + c, 8 + f);
    } else if (j < 1712) {
        int t = j - 1448;
        int f = t / 33, c = t - f * 33;
        e = make_int4(2, 33, f * 1000 * 33 + c, 18 + f);
    } else if (j < 1725) {
        e = make_int4(3, j - 1712, 0, 0);
    } else {
        e = make_int4(4, 0, 0, 0);
    }
    g_tab[j] = e;
}

// ---------------------------------------------------------------------------
// 1. Gather (table-driven)
// ---------------------------------------------------------------------------
__global__ void gather_kernel(const int* __restrict__ sparse,
                              const float* __restrict__ dense,
                              const float* __restrict__ emb_a,
                              const float* __restrict__ emb_b,
                              const float* __restrict__ emb_c)
{
    __shared__ int sp[26];
    const int row = blockIdx.x;
    if (threadIdx.x < 26) sp[threadIdx.x] = sparse[row * 26 + threadIdx.x];
    __syncthreads();

    float* hr = g_h + (size_t)row * LDH;
    for (int j = threadIdx.x; j < LDH; j += blockDim.x) {
        int4 e = g_tab[j];
        float v;
        if (e.x == 0)      v = emb_a[(size_t)e.z + (size_t)sp[e.w] * e.y];
        else if (e.x == 1) v = emb_b[(size_t)e.z + (size_t)sp[e.w] * e.y];
        else if (e.x == 2) v = emb_c[(size_t)e.z + (size_t)sp[e.w] * e.y];
        else if (e.x == 3) v = dense[row * 13 + e.y];
        else               v = 0.0f;
        hr[j] = v;
    }
}

// ---------------------------------------------------------------------------
// 2. Column partial stats (h only; GEMM layers fuse stats into epilogue)
// ---------------------------------------------------------------------------
__global__ void colstats_partial(const float* __restrict__ X, int ld, int ncols)
{
    int col = blockIdx.x * blockDim.x + threadIdx.x;
    if (col >= ncols) return;
    int r0 = blockIdx.y * ROWS_PER_CHUNK;
    float s = 0.f, q = 0.f;
    const float* p = X + (size_t)r0 * ld + col;
    for (int r = 0; r < ROWS_PER_CHUNK; r++) {
        float v = p[(size_t)r * ld];
        s += v; q += v * v;
    }
    g_psum[blockIdx.y * ncols + col] = s;
    g_psq [blockIdx.y * ncols + col] = q;
}

// ---------------------------------------------------------------------------
// 2b. Fused stats-finalize + normalize (+relu) + optional fp32/fp16 emit.
//     Each block: 64-column panel x 128-row tile. Stats recomputed per block
//     from partials (deterministic; identical across blocks of same panel).
//     grid = (ncols/64, B/128), block = 256.
// ---------------------------------------------------------------------------
__global__ __launch_bounds__(256)
void bn_fused(const float4* __restrict__ X, float4* __restrict__ Xout,
              uint2* __restrict__ ofp, int ncols, int nchunks, int relu)
{
    __shared__ float ms[64], rs[64];
    const int tid = threadIdx.x;
    const int c0 = blockIdx.x * 64;
    if (tid < 64) {
        int col = c0 + tid;
        float s = 0.f, q = 0.f;
        for (int c = 0; c < nchunks; c++) {
            s += g_psum[c * ncols + col];
            q += g_psq [c * ncols + col];
        }
        float mean = s * (1.0f / B);
        float var  = q * (1.0f / B) - mean * mean;
        ms[tid] = mean;
        rs[tid] = rsqrtf(var + EPS);
    }
    __syncthreads();

    const int ld4 = ncols >> 2;
    const int r0  = blockIdx.y * 128;
    #pragma unroll 2
    for (int i = tid; i < 128 * 16; i += 256) {
        int row = r0 + (i >> 4);
        int cp  = i & 15;
        size_t idx = (size_t)row * ld4 + (c0 >> 2) + cp;
        float4 v = X[idx];
        int cc = cp * 4;
        v.x = (v.x - ms[cc + 0]) * rs[cc + 0];
        v.y = (v.y - ms[cc + 1]) * rs[cc + 1];
        v.z = (v.z - ms[cc + 2]) * rs[cc + 2];
        v.w = (v.w - ms[cc + 3]) * rs[cc + 3];
        if (relu) {
            v.x = fmaxf(v.x, 0.f); v.y = fmaxf(v.y, 0.f);
            v.z = fmaxf(v.z, 0.f); v.w = fmaxf(v.w, 0.f);
        }
        if (Xout) Xout[idx] = v;
        if (ofp) {
            __half2 p0 = __floats2half2_rn(v.x, v.y);
            __half2 p1 = __floats2half2_rn(v.z, v.w);
            uint2 u;
            u.x = *(uint32_t*)&p0;
            u.y = *(uint32_t*)&p1;
            ofp[idx] = u;
        }
    }
}

// ---------------------------------------------------------------------------
// 3. Weight transpose + fp16 convert. W: [K x N] -> out: [N x K]
// ---------------------------------------------------------------------------
__global__ void wt_conv(const float* __restrict__ W, int K, int N, int Klim,
                        __half* __restrict__ of)
{
    __shared__ float t[32][33];
    int k0 = blockIdx.x * 32, n0 = blockIdx.y * 32;
    for (int i = threadIdx.y; i < 32; i += 8) {
        int k = k0 + i;
        t[i][threadIdx.x] = (k < Klim) ? W[(size_t)k * N + n0 + threadIdx.x] : 0.f;
    }
    __syncthreads();
    for (int i = threadIdx.y; i < 32; i += 8) {
        int n = n0 + i, k = k0 + threadIdx.x;
        of[(size_t)n * K + k] = __float2half_rn(t[threadIdx.x][i]);
    }
}

// ---------------------------------------------------------------------------
// 4. Fused cross network + cross head (2 barriers per layer)
// ---------------------------------------------------------------------------
__global__ __launch_bounds__(256)
void cross_kernel(const float* __restrict__ cw,
                  const float* __restrict__ cb,
                  const float* __restrict__ wout)
{
    __shared__ float x0[NF];
    __shared__ float xi[NF];
    __shared__ float red[8];
    const int row  = blockIdx.x;
    const int tid  = threadIdx.x;
    const int lane = tid & 31;
    const int warp = tid >> 5;

    const float* hr = g_h + (size_t)row * LDH;
    for (int j = tid; j < NF; j += 256) {
        float v = hr[j];
        x0[j] = v; xi[j] = v;
    }
    __syncthreads();

    for (int L = 0; L < NCROSS; L++) {
        const float* w = cw + L * NF;
        float s = 0.f;
        for (int j = tid; j < NF; j += 256) s += xi[j] * w[j];
        #pragma unroll
        for (int off = 16; off > 0; off >>= 1)
            s += __shfl_xor_sync(0xffffffffu, s, off);
        if (lane == 0) red[warp] = s;
        __syncthreads();
        float dot = red[0] + red[1] + red[2] + red[3]
                  + red[4] + red[5] + red[6] + red[7];
        const float* b = cb + L * NF;
        for (int j = tid; j < NF; j += 256)
            xi[j] = fmaf(x0[j], dot, b[j] + xi[j]);
        __syncthreads();
    }

    float s = 0.f;
    for (int j = tid; j < NF; j += 256) s += xi[j] * wout[j];
    #pragma unroll
    for (int off = 16; off > 0; off >>= 1)
        s += __shfl_xor_sync(0xffffffffu, s, off);
    if (lane == 0) red[warp] = s;
    __syncthreads();
    if (tid == 0)
        g_cross_partial[row] = red[0] + red[1] + red[2] + red[3]
                             + red[4] + red[5] + red[6] + red[7];
}

// ---------------------------------------------------------------------------
// 5. fp16 mma.sync GEMM + bias + fused column stats.
//    BM=BN=128, BK=32, 4-stage cp.async pipeline, ldmatrix, 80B pitch.
// ---------------------------------------------------------------------------
#define ARRSZ  (128 * 80)
#define BUFSZ  (2 * ARRSZ)
#define NSTAGE 4
#define GEMM_SMEM (NSTAGE * BUFSZ)   // 81920 B

__global__ __launch_bounds__(256, 2)
void hgemm(int K8, int nch,
           const uint4* __restrict__ A, const uint4* __restrict__ Bm,
           const float* __restrict__ bias, float* __restrict__ C, int ldc)
{
    extern __shared__ char dsm[];
    const uint32_t sb = smem_u32(dsm);

    const int tid  = threadIdx.x;
    const int warp = tid >> 5;
    const int lane = tid & 31;
    const int wm = warp >> 2;
    const int wn = warp & 3;
    const int m0 = blockIdx.y * 128;
    const int n0 = blockIdx.x * 128;

    const uint32_t aoff = (uint32_t)(wm * 64 + (lane & 15)) * 80u
                        + ((lane >> 4) * 16u);
    const uint32_t boff = (uint32_t)(wn * 32 + ((lane >> 4) << 3) + (lane & 7)) * 80u
                        + (((lane >> 3) & 1) * 16u);

    float acc[4][4][4] = {};

    auto load_tile = [&](int ch, int buf) {
        const uint32_t bb = sb + (uint32_t)buf * BUFSZ;
        const int k0u = ch * 4;
        #pragma unroll
        for (int i = 0; i < 4; i++) {
            const int rem = ((i & 1) << 8) + tid;
            const int r = rem >> 2, c = rem & 3;
            uint32_t sa = bb + (uint32_t)((i >> 1) * ARRSZ) + (uint32_t)r * 80u + c * 16u;
            const uint4* gp = (i < 2 ? A + (size_t)(m0 + r) * K8
                                     : Bm + (size_t)(n0 + r) * K8) + k0u + c;
            CP_ASYNC16(sa, gp);
        }
        CP_COMMIT();
    };

    load_tile(0, 0);
    load_tile(1, 1);
    load_tile(2, 2);

    for (int ch = 0; ch < nch; ch++) {
        CP_WAIT2();
        __syncthreads();
        if (ch + 3 < nch) load_tile(ch + 3, (ch + 3) % NSTAGE);
        else              CP_COMMIT();         // keep one group per iteration

        const uint32_t bb = sb + (uint32_t)(ch % NSTAGE) * BUFSZ;
        #pragma unroll
        for (int ks = 0; ks < 2; ks++) {
            uint32_t bh[4][2];
            #pragma unroll
            for (int p = 0; p < 2; p++) {
                uint32_t ad = bb + ARRSZ + boff + (uint32_t)p * (16 * 80) + ks * 32;
                LDSM4(bh[2*p][0], bh[2*p][1], bh[2*p+1][0], bh[2*p+1][1], ad);
            }
            #pragma unroll
            for (int mt = 0; mt < 4; mt++) {
                uint32_t ad = bb + aoff + (uint32_t)mt * (16 * 80) + ks * 32;
                uint32_t af[4];
                LDSM4(af[0], af[1], af[2], af[3], ad);
                #pragma unroll
                for (int nt = 0; nt < 4; nt++)
                    MMA_F16(acc[mt][nt], af, bh[nt]);
            }
        }
        __syncthreads();
    }

    // ---- epilogue: + bias, store, column sums/sqsums ----
    const int tr = lane >> 2;
    const int tc = (lane & 3) * 2;
    float cs[4][2] = {}, cq[4][2] = {};

    #pragma unroll
    for (int mt = 0; mt < 4; mt++) {
        int row = m0 + wm * 64 + mt * 16 + tr;
        #pragma unroll
        for (int nt = 0; nt < 4; nt++) {
            int col = n0 + wn * 32 + nt * 8 + tc;
            float b0 = bias[col], b1 = bias[col + 1];
            float a0 = acc[mt][nt][0] + b0;
            float a1 = acc[mt][nt][1] + b1;
            float a2 = acc[mt][nt][2] + b0;
            float a3 = acc[mt][nt][3] + b1;
            *(float2*)(C + (size_t)row * ldc + col)       = make_float2(a0, a1);
            *(float2*)(C + (size_t)(row + 8) * ldc + col) = make_float2(a2, a3);
            cs[nt][0] += a0 + a2;  cq[nt][0] += a0 * a0 + a2 * a2;
            cs[nt][1] += a1 + a3;  cq[nt][1] += a1 * a1 + a3 * a3;
        }
    }
    #pragma unroll
    for (int off = 4; off <= 16; off <<= 1) {
        #pragma unroll
        for (int nt = 0; nt < 4; nt++) {
            cs[nt][0] += __shfl_xor_sync(0xffffffffu, cs[nt][0], off);
            cs[nt][1] += __shfl_xor_sync(0xffffffffu, cs[nt][1], off);
            cq[nt][0] += __shfl_xor_sync(0xffffffffu, cq[nt][0], off);
            cq[nt][1] += __shfl_xor_sync(0xffffffffu, cq[nt][1], off);
        }
    }
    float* cr = (float*)dsm;   // [wm][s/q][128] = 1024 floats
    __syncthreads();
    if (tr == 0) {
        #pragma unroll
        for (int nt = 0; nt < 4; nt++) {
            int col = wn * 32 + nt * 8 + tc;
            cr[(wm * 2 + 0) * 128 + col]     = cs[nt][0];
            cr[(wm * 2 + 0) * 128 + col + 1] = cs[nt][1];
            cr[(wm * 2 + 1) * 128 + col]     = cq[nt][0];
            cr[(wm * 2 + 1) * 128 + col + 1] = cq[nt][1];
        }
    }
    __syncthreads();
    if (tid < 128) {
        float s = cr[tid] + cr[256 + tid];
        float q = cr[128 + tid] + cr[384 + tid];
        g_psum[blockIdx.y * ldc + n0 + tid] = s;
        g_psq [blockIdx.y * ldc + n0 + tid] = q;
    }
}

// ---------------------------------------------------------------------------
// 6. Final head
// ---------------------------------------------------------------------------
__global__ void final_kernel(const float* __restrict__ wout_tail,
                             float* __restrict__ out)
{
    int row  = blockIdx.x * 8 + (threadIdx.x >> 5);
    int lane = threadIdx.x & 31;
    const float* r = g_z3 + (size_t)row * N3;
    float s = 0.f;
    #pragma unroll
    for (int j = lane; j < N3; j += 32) s += r[j] * wout_tail[j];
    #pragma unroll
    for (int off = 16; off > 0; off >>= 1)
        s += __shfl_down_sync(0xffffffffu, s, off);
    if (lane == 0) {
        float z = s + g_cross_partial[row];
        out[row] = 1.0f / (1.0f + expf(-z));
    }
}

// ---------------------------------------------------------------------------
// Launcher (stream-forked: weights+cross branch overlaps the GEMM chain)
// ---------------------------------------------------------------------------
extern "C" void kernel_launch(void* const* d_in, const int* in_sizes, int n_in,
                              void* d_out, int out_size)
{
    const int*   sparse  = (const int*)  d_in[0];
    const float* dense   = (const float*)d_in[1];
    const float* emb_a   = (const float*)d_in[2];
    const float* emb_b   = (const float*)d_in[3];
    const float* emb_c   = (const float*)d_in[4];
    const float* cross_w = (const float*)d_in[5];
    const float* cross_b = (const float*)d_in[6];
    const float* W1      = (const float*)d_in[7];
    const float* b1      = (const float*)d_in[8];
    const float* W2      = (const float*)d_in[9];
    const float* b2      = (const float*)d_in[10];
    const float* W3      = (const float*)d_in[11];
    const float* b3      = (const float*)d_in[12];
    const float* Wout    = (const float*)d_in[13];
    float* out = (float*)d_out;

    static cudaStream_t s1 = nullptr;
    static cudaEvent_t e_fork, e_wt, e_bnh, e_cross;
    if (!s1) {
        cudaFuncSetAttribute(hgemm, cudaFuncAttributeMaxDynamicSharedMemorySize, GEMM_SMEM);
        cudaStreamCreateWithFlags(&s1, cudaStreamNonBlocking);
        cudaEventCreateWithFlags(&e_fork,  cudaEventDisableTiming);
        cudaEventCreateWithFlags(&e_wt,    cudaEventDisableTiming);
        cudaEventCreateWithFlags(&e_bnh,   cudaEventDisableTiming);
        cudaEventCreateWithFlags(&e_cross, cudaEventDisableTiming);
    }

    float *ph, *pz1, *pz2, *pz3;
    cudaGetSymbolAddress((void**)&ph,  g_h);
    cudaGetSymbolAddress((void**)&pz1, g_z1);
    cudaGetSymbolAddress((void**)&pz2, g_z2);
    cudaGetSymbolAddress((void**)&pz3, g_z3);
    uint4 *paf, *pz1f, *pz2f, *pw1f, *pw2f, *pw3f;
    cudaGetSymbolAddress((void**)&paf,  g_af);
    cudaGetSymbolAddress((void**)&pz1f, g_z1f);
    cudaGetSymbolAddress((void**)&pz2f, g_z2f);
    cudaGetSymbolAddress((void**)&pw1f, g_w1f);
    cudaGetSymbolAddress((void**)&pw2f, g_w2f);
    cudaGetSymbolAddress((void**)&pw3f, g_w3f);

    // ---- fork: side stream handles weight prep, later the cross branch ----
    cudaEventRecord(e_fork, 0);
    cudaStreamWaitEvent(s1, e_fork, 0);

    // side stream: weight transpose/convert
    {
        dim3 blk(32, 8);
        dim3 g1(LDH / 32, N1 / 32);
        wt_conv<<<g1, blk, 0, s1>>>(W1, LDH, N1, NF, (__half*)pw1f);
        dim3 g2(N1 / 32, N2 / 32);
        wt_conv<<<g2, blk, 0, s1>>>(W2, N1, N2, N1, (__half*)pw2f);
        dim3 g3(N2 / 32, N3 / 32);
        wt_conv<<<g3, blk, 0, s1>>>(W3, N2, N3, N2, (__half*)pw3f);
        cudaEventRecord(e_wt, s1);
    }

    // main stream: gather + h stats + fused BN (fp32 h + fp16 af)
    build_tab<<<(LDH + 255) / 256, 256>>>();
    gather_kernel<<<B, 256>>>(sparse, dense, emb_a, emb_b, emb_c);
    {
        dim3 g((LDH + 127) / 128, NCHUNK);
        colstats_partial<<<g, 128>>>(ph, LDH, LDH);
        dim3 gb(LDH / 64, B / 128);
        bn_fused<<<gb, 256>>>((float4*)ph, (float4*)ph, (uint2*)paf, LDH, NCHUNK, 0);
    }
    cudaEventRecord(e_bnh, 0);

    // side stream: cross network (parallel with GEMM chain)
    cudaStreamWaitEvent(s1, e_bnh, 0);
    cross_kernel<<<B, 256, 0, s1>>>(cross_w, cross_b, Wout);
    cudaEventRecord(e_cross, s1);

    // main stream: GEMM chain (needs weights)
    cudaStreamWaitEvent(0, e_wt, 0);
    {
        dim3 grid(N1 / 128, B / 128);
        hgemm<<<grid, 256, GEMM_SMEM>>>(LDH / 8, LDH / 32, paf, pw1f, b1, pz1, N1);
        dim3 gb(N1 / 64, B / 128);
        bn_fused<<<gb, 256>>>((float4*)pz1, (float4*)nullptr, (uint2*)pz1f, N1, GCHUNK, 1);
    }
    {
        dim3 grid(N2 / 128, B / 128);
        hgemm<<<grid, 256, GEMM_SMEM>>>(N1 / 8, N1 / 32, pz1f, pw2f, b2, pz2, N2);
        dim3 gb(N2 / 64, B / 128);
        bn_fused<<<gb, 256>>>((float4*)pz2, (float4*)nullptr, (uint2*)pz2f, N2, GCHUNK, 1);
    }
    {
        dim3 grid(N3 / 128, B / 128);
        hgemm<<<grid, 256, GEMM_SMEM>>>(N2 / 8, N2 / 32, pz2f, pw3f, b3, pz3, N3);
        dim3 gb(N3 / 64, B / 128);
        bn_fused<<<gb, 256>>>((float4*)pz3, (float4*)pz3, (uint2*)nullptr, N3, GCHUNK, 1);
    }

    // join: final head needs cross_partial + z3
    cudaStreamWaitEvent(0, e_cross, 0);
    final_kernel<<<B / 8, 256>>>(Wout + NF, out);
}